// round 11
// baseline (speedup 1.0000x reference)
#include <cuda_runtime.h>
#include <cuda_fp16.h>
#include <math.h>
#include <stdint.h>

#define NN   100000
#define NE   250000
#define NB   2000
#define FIN  75
#define DIM  32
#define HID  128
#define NOUT 1024           // DIM*DIM
#define MPAD 250112         // 1954 * 128

// ---------------- scratch (static __device__, no allocation) ----------------
__device__ __align__(16) __half g_ewb[(size_t)MPAD * NOUT];  // edge weights fp16, [o][i] per edge
__device__ __align__(16) __half g_w2b[NOUT * HID];           // W2 fp16, column-permuted (c' = o*32+i)
__device__ float g_b2p[NOUT];                                // b2 permuted
__device__ float g_x[NN * DIM];                 // node state
__device__ float g_acc[NN * DIM];               // conv scatter accumulator
__device__ int   g_cnt[NN];                     // in-degree
__device__ int   g_goff[NB + 1];                // graph offsets (graph_index is sorted)
__device__ float g_h2[NB * DIM];                // set2set LSTM h
__device__ float g_c2[NB * DIM];                // set2set LSTM c
__device__ float g_qstar[NB * 2 * DIM];         // set2set q_star
// transposed weights
__device__ float g_w0T[FIN * DIM];
__device__ float g_w1T[11 * HID];
__device__ float g_wihT[DIM * 96];
__device__ float g_whhT[DIM * 96];
__device__ float g_lwihT[64 * 128];
__device__ float g_lwhhT[DIM * 128];

__device__ __forceinline__ uint32_t smem_u32(const void* p) {
    uint32_t a;
    asm("{ .reg .u64 t; cvta.to.shared.u64 t, %1; cvt.u32.u64 %0, t; }" : "=r"(a) : "l"(p));
    return a;
}
__device__ __forceinline__ void cp_async16(uint32_t dst, const void* src) {
    asm volatile("cp.async.cg.shared.global [%0], [%1], 16;" :: "r"(dst), "l"(src));
}
#define CP_COMMIT() asm volatile("cp.async.commit_group;" ::: "memory")
#define CP_WAIT0()  asm volatile("cp.async.wait_group 0;" ::: "memory")

// ---------------- prep: transposes + fp16 W2 with column permutation ----------------
__global__ void prep_kernel(const float* __restrict__ w0, const float* __restrict__ w1,
                            const float* __restrict__ gwih, const float* __restrict__ gwhh,
                            const float* __restrict__ lwih, const float* __restrict__ lwhh,
                            const float* __restrict__ w2, const float* __restrict__ b2) {
    int t = blockIdx.x * 256 + threadIdx.x;
    if (t < FIN * DIM) { int i = t / DIM, o = t % DIM; g_w0T[t] = w0[o * FIN + i]; }
    if (t < 11 * HID)  { int i = t / HID, j = t % HID; g_w1T[t] = w1[j * 11 + i]; }
    if (t < DIM * 96)  { int i = t / 96,  r = t % 96;  g_wihT[t] = gwih[r * DIM + i]; g_whhT[t] = gwhh[r * DIM + i]; }
    if (t < 64 * 128)  { int i = t / 128, r = t % 128; g_lwihT[t] = lwih[r * 64 + i]; }
    if (t < DIM * 128) { int i = t / 128, r = t % 128; g_lwhhT[t] = lwhh[r * DIM + i]; }
    if (t < NOUT) { int corig = (t & 31) * 32 + (t >> 5); g_b2p[t] = b2[corig]; }
    if (t < NOUT * HID) {
        int cp = t / HID, k = t % HID;
        int corig = (cp & 31) * 32 + (cp >> 5);      // cp = o*32+i holds original column i*32+o
        g_w2b[t] = __float2half(w2[corig * HID + k]);
    }
}

__global__ void deg_kernel(const int* __restrict__ ei) {
    int e = blockIdx.x * 256 + threadIdx.x;
    if (e < NE) atomicAdd(&g_cnt[ei[NE + e]], 1);
}

__global__ void goff_kernel(const int* __restrict__ gidx) {
    int g = blockIdx.x * 256 + threadIdx.x;
    if (g > NB) return;
    int lo = 0, hi = NN;
    while (lo < hi) { int mid = (lo + hi) >> 1; if (gidx[mid] < g) lo = mid + 1; else hi = mid; }
    g_goff[g] = lo;
}

// ---------------- lin0: x = relu(nf @ W0^T + b); also zeroes g_cnt / g_acc ----------------
__global__ void lin0_kernel(const float* __restrict__ nf, const float* __restrict__ b) {
    int warp = threadIdx.x >> 5;
    int node = blockIdx.x * 8 + warp;
    int o = threadIdx.x & 31;
    __shared__ float sf[8][FIN + 1];
    int base = blockIdx.x * 8;
    for (int idx = threadIdx.x; idx < 8 * FIN; idx += 256) {
        int nn = base + idx / FIN;
        sf[idx / FIN][idx % FIN] = (nn < NN) ? nf[(size_t)nn * FIN + idx % FIN] : 0.f;
    }
    __syncthreads();
    if (node >= NN) return;
    float acc = b[o];
#pragma unroll
    for (int i = 0; i < FIN; i++) acc = fmaf(sf[warp][i], g_w0T[i * DIM + o], acc);
    g_x[node * DIM + o] = fmaxf(acc, 0.f);
    g_acc[node * DIM + o] = 0.f;
    if (o == 0) g_cnt[node] = 0;
}

// ---- fused GEMM: per CTA of 128 edges; double-buffered B via cp.async, C staged into spent B buffer ----
#define SM_A     0
#define SM_B0    32768
#define SM_B1    65536
#define SM_SEF   65536                    // prologue aux lives inside B1
#define SM_W1T   (65536 + 6144)
#define SM_B1A   (65536 + 6144 + 5632)
#define SM_BIAS  98304                    // 1024 floats
#define SMEM_GEMM_TOTAL 102400

__device__ __forceinline__ void mma_fp16(float* c, const uint32_t* a, uint32_t b0, uint32_t b1) {
    asm volatile(
        "mma.sync.aligned.m16n8k16.row.col.f32.f16.f16.f32 "
        "{%0,%1,%2,%3}, {%4,%5,%6,%7}, {%8,%9}, {%0,%1,%2,%3};"
        : "+f"(c[0]), "+f"(c[1]), "+f"(c[2]), "+f"(c[3])
        : "r"(a[0]), "r"(a[1]), "r"(a[2]), "r"(a[3]), "r"(b0), "r"(b1));
}

__global__ void __launch_bounds__(256) gemm_fused_kernel(const float* __restrict__ ef,
                                                         const float* __restrict__ b1) {
    extern __shared__ __align__(16) char smem[];
    uint32_t sbase = smem_u32(smem);
    float* sef   = (float*)(smem + SM_SEF);
    float* sw1t  = (float*)(smem + SM_W1T);
    float* sb1   = (float*)(smem + SM_B1A);
    float* sbias = (float*)(smem + SM_BIAS);
    int tid = threadIdx.x, lane = tid & 31, wid = tid >> 5;
    int e0 = blockIdx.x * 128;

    // prefetch B slab 0 into B0 (overlaps with aux loads + A build)
#pragma unroll
    for (int it = 0; it < 8; it++) {
        int idx = tid + it * 256;
        int row = idx >> 4, c = idx & 15;
        int cs = (c & 8) | ((c ^ row) & 7);
        cp_async16(sbase + SM_B0 + row * 256 + cs * 16,
                   (const char*)g_w2b + (((size_t)row) * HID + c * 8) * 2);
    }
    CP_COMMIT();

    // ---- prologue aux loads (into B1 region; consumed before B1 is first prefetched) ----
    for (int idx = tid; idx < 128 * 11; idx += 256) {
        int r = idx / 11, i = idx % 11;
        int e = e0 + r;
        sef[r * 12 + i] = (e < NE) ? ef[(size_t)e * 11 + i] : 0.f;
    }
    for (int idx = tid; idx < 11 * HID; idx += 256) sw1t[idx] = g_w1T[idx];
    if (tid < 128) sb1[tid] = b1[tid];
#pragma unroll
    for (int l = 0; l < 4; l++) sbias[tid + l * 256] = g_b2p[tid + l * 256];
    __syncthreads();

    // ---- build A tile: hw = relu(ef @ W1^T + b1), fp16, xor-swizzled ----
#pragma unroll
    for (int ci = 0; ci < 8; ci++) {
        int cidx = tid + ci * 256;
        int row = cidx >> 4, c = cidx & 15;
        int k0 = c * 8;
        float v[8];
#pragma unroll
        for (int j = 0; j < 8; j++) v[j] = sb1[k0 + j];
#pragma unroll
        for (int i = 0; i < 11; i++) {
            float e_ = sef[row * 12 + i];
#pragma unroll
            for (int j = 0; j < 8; j++) v[j] = fmaf(e_, sw1t[i * HID + k0 + j], v[j]);
        }
        uint32_t p[4];
#pragma unroll
        for (int j = 0; j < 4; j++) {
            __half2 h = __floats2half2_rn(fmaxf(v[2 * j], 0.f), fmaxf(v[2 * j + 1], 0.f));
            p[j] = *(uint32_t*)&h;
        }
        int cs = (c & 8) | ((c ^ row) & 7);
        *(uint4*)(smem + SM_A + row * 256 + cs * 16) = make_uint4(p[0], p[1], p[2], p[3]);
    }
    CP_WAIT0();
    __syncthreads();      // A built, B0 ready, aux consumed

    int wm = (wid & 3) * 32;
    int wn = (wid >> 2) * 64;
    int g = lane >> 2, tg = lane & 3;

    for (int nb = 0; nb < 8; nb++) {
        uint32_t cur = (nb & 1) ? SM_B1 : SM_B0;
        uint32_t alt = (nb & 1) ? SM_B0 : SM_B1;

        // prefetch next slab into alt buffer (alt's previous contents already consumed+synced)
        if (nb < 7) {
#pragma unroll
            for (int it = 0; it < 8; it++) {
                int idx = tid + it * 256;
                int row = idx >> 4, c = idx & 15;
                int cs = (c & 8) | ((c ^ row) & 7);
                cp_async16(sbase + alt + row * 256 + cs * 16,
                           (const char*)g_w2b + (((size_t)((nb + 1) * 128 + row)) * HID + c * 8) * 2);
            }
            CP_COMMIT();
        }

        float acc[2][8][4];
#pragma unroll
        for (int mb = 0; mb < 2; mb++)
#pragma unroll
            for (int nbb = 0; nbb < 8; nbb++)
#pragma unroll
                for (int q = 0; q < 4; q++) acc[mb][nbb][q] = 0.f;

#pragma unroll
        for (int ks = 0; ks < 8; ks++) {
            int ck0 = ks * 2;
            uint32_t a[2][4], b[4][4];
#pragma unroll
            for (int mb = 0; mb < 2; mb++) {
                int row = wm + mb * 16 + (lane & 7) + ((lane >> 3) & 1) * 8;
                int ck = ck0 + (lane >> 4);
                int cs = (ck & 8) | ((ck ^ row) & 7);
                uint32_t addr = sbase + SM_A + row * 256 + cs * 16;
                asm volatile("ldmatrix.sync.aligned.m8n8.x4.shared.b16 {%0,%1,%2,%3}, [%4];"
                             : "=r"(a[mb][0]), "=r"(a[mb][1]), "=r"(a[mb][2]), "=r"(a[mb][3])
                             : "r"(addr));
            }
#pragma unroll
            for (int nb4 = 0; nb4 < 4; nb4++) {
                int t = lane >> 3, r = lane & 7;
                int n = wn + nb4 * 16 + r + (t >> 1) * 8;
                int ck = ck0 + (t & 1);
                int cs = (ck & 8) | ((ck ^ n) & 7);
                uint32_t addr = sbase + cur + n * 256 + cs * 16;
                asm volatile("ldmatrix.sync.aligned.m8n8.x4.shared.b16 {%0,%1,%2,%3}, [%4];"
                             : "=r"(b[nb4][0]), "=r"(b[nb4][1]), "=r"(b[nb4][2]), "=r"(b[nb4][3])
                             : "r"(addr));
            }
#pragma unroll
            for (int mb = 0; mb < 2; mb++)
#pragma unroll
                for (int nbb = 0; nbb < 8; nbb++)
                    mma_fp16(acc[mb][nbb], a[mb], b[nbb >> 1][(nbb & 1) * 2], b[nbb >> 1][(nbb & 1) * 2 + 1]);
        }
        __syncthreads();   // all warps done reading cur B

        // stage C (fp16 + bias) into the spent cur buffer, xor-swizzled 4B stores
#pragma unroll
        for (int mb = 0; mb < 2; mb++)
#pragma unroll
            for (int nbb = 0; nbb < 8; nbb++) {
                int rowl = wm + mb * 16 + g;
                int nl = wn + nbb * 8 + tg * 2;
                float bb0 = sbias[nb * 128 + nl], bb1 = sbias[nb * 128 + nl + 1];
                float* c = acc[mb][nbb];
                __half2 p0 = __floats2half2_rn(c[0] + bb0, c[1] + bb1);
                __half2 p1 = __floats2half2_rn(c[2] + bb0, c[3] + bb1);
                int byo = nl * 2;
                int cc = byo >> 4;
                int cs0 = (cc & 8) | ((cc ^ rowl) & 7);
                int cs1 = (cc & 8) | ((cc ^ (rowl + 8)) & 7);
                *(uint32_t*)(smem + cur + rowl * 256 + cs0 * 16 + (byo & 15)) = *(uint32_t*)&p0;
                *(uint32_t*)(smem + cur + (rowl + 8) * 256 + cs1 * 16 + (byo & 15)) = *(uint32_t*)&p1;
            }
        __syncthreads();

        // coalesced global write of this 128-column slab
        __half* dst = g_ewb + (size_t)e0 * NOUT + nb * 128;
#pragma unroll
        for (int it = 0; it < 8; it++) {
            int idx = tid + it * 256;
            int row = idx >> 4, c = idx & 15;
            int cs = (c & 8) | ((c ^ row) & 7);
            uint4 v = *(const uint4*)(smem + cur + row * 256 + cs * 16);
            *(uint4*)(dst + (size_t)row * NOUT + c * 8) = v;
        }
        if (nb < 7) CP_WAIT0();
        __syncthreads();
    }
}

// ---------------- NNConv: warp per edge, lane = output channel, [o][i] vectorized loads ----------------
__global__ void conv_kernel(const int* __restrict__ ei) {
    int e = blockIdx.x * 8 + (threadIdx.x >> 5);
    if (e >= NE) return;
    int o = threadIdx.x & 31;
    int src = ei[e];
    int dst = ei[NE + e];
    float xv = g_x[src * DIM + o];
    const uint4* w = (const uint4*)(g_ewb + (size_t)e * NOUT + o * 32);
    uint4 w0 = w[0], w1 = w[1], w2 = w[2], w3 = w[3];
    uint32_t ws[16] = {w0.x, w0.y, w0.z, w0.w, w1.x, w1.y, w1.z, w1.w,
                       w2.x, w2.y, w2.z, w2.w, w3.x, w3.y, w3.z, w3.w};
    float acc = 0.f;
#pragma unroll
    for (int i = 0; i < 16; i++) {
        float2 wp = __half22float2(*(__half2*)&ws[i]);
        float x0 = __shfl_sync(0xffffffffu, xv, 2 * i);
        float x1 = __shfl_sync(0xffffffffu, xv, 2 * i + 1);
        acc = fmaf(x0, wp.x, fmaf(x1, wp.y, acc));
    }
    atomicAdd(&g_acc[dst * DIM + o], acc);
}

// ---------------- scatter-mean + relu + GRU (in-place on g_x); zeroes g_acc after read ----------------
__global__ void gru_kernel(const float* __restrict__ cbias, const float* __restrict__ bih,
                           const float* __restrict__ bhh) {
    int warp = threadIdx.x >> 5;
    int node = blockIdx.x * 8 + warp;
    int o = threadIdx.x & 31;
    __shared__ float sm[8][DIM], sh[8][DIM];
    if (node < NN) {
        int c = g_cnt[node]; if (c < 1) c = 1;
        sm[warp][o] = fmaxf(g_acc[node * DIM + o] / (float)c + cbias[o], 0.f);
        sh[warp][o] = g_x[node * DIM + o];
        g_acc[node * DIM + o] = 0.f;   // ready for next conv iteration
    }
    __syncthreads();
    if (node >= NN) return;
    float gir = bih[o], giz = bih[DIM + o], gin = bih[2 * DIM + o];
    float ghr = bhh[o], ghz = bhh[DIM + o], ghn = bhh[2 * DIM + o];
#pragma unroll
    for (int i = 0; i < DIM; i++) {
        float mi = sm[warp][i], hi = sh[warp][i];
        gir = fmaf(mi, g_wihT[i * 96 + o], gir);
        giz = fmaf(mi, g_wihT[i * 96 + DIM + o], giz);
        gin = fmaf(mi, g_wihT[i * 96 + 2 * DIM + o], gin);
        ghr = fmaf(hi, g_whhT[i * 96 + o], ghr);
        ghz = fmaf(hi, g_whhT[i * 96 + DIM + o], ghz);
        ghn = fmaf(hi, g_whhT[i * 96 + 2 * DIM + o], ghn);
    }
    float r = 1.f / (1.f + expf(-(gir + ghr)));
    float z = 1.f / (1.f + expf(-(giz + ghz)));
    float nv = tanhf(gin + r * ghn);
    g_x[node * DIM + o] = (1.f - z) * nv + z * sh[warp][o];
}

__global__ void zero_s2s_kernel() {
    int i = blockIdx.x * 256 + threadIdx.x;
    if (i < NB * DIM) { g_h2[i] = 0.f; g_c2[i] = 0.f; }
    if (i < NB * 2 * DIM) g_qstar[i] = 0.f;
}

// ---------------- Set2Set LSTM cell ----------------
__global__ void lstm_kernel(const float* __restrict__ bih, const float* __restrict__ bhh) {
    int warp = threadIdx.x >> 5;
    int b = blockIdx.x * 8 + warp;
    int o = threadIdx.x & 31;
    __shared__ float sq[8][64], shh[8][DIM];
    if (b < NB) {
        sq[warp][o]      = g_qstar[b * 64 + o];
        sq[warp][32 + o] = g_qstar[b * 64 + 32 + o];
        shh[warp][o]     = g_h2[b * DIM + o];
    }
    __syncthreads();
    if (b >= NB) return;
    float gi = bih[o] + bhh[o];
    float gf = bih[32 + o] + bhh[32 + o];
    float gg = bih[64 + o] + bhh[64 + o];
    float go = bih[96 + o] + bhh[96 + o];
#pragma unroll
    for (int i = 0; i < 64; i++) {
        float v = sq[warp][i];
        gi = fmaf(v, g_lwihT[i * 128 + o], gi);
        gf = fmaf(v, g_lwihT[i * 128 + 32 + o], gf);
        gg = fmaf(v, g_lwihT[i * 128 + 64 + o], gg);
        go = fmaf(v, g_lwihT[i * 128 + 96 + o], go);
    }
#pragma unroll
    for (int i = 0; i < DIM; i++) {
        float v = shh[warp][i];
        gi = fmaf(v, g_lwhhT[i * 128 + o], gi);
        gf = fmaf(v, g_lwhhT[i * 128 + 32 + o], gf);
        gg = fmaf(v, g_lwhhT[i * 128 + 64 + o], gg);
        go = fmaf(v, g_lwhhT[i * 128 + 96 + o], go);
    }
    float si = 1.f / (1.f + expf(-gi));
    float sf = 1.f / (1.f + expf(-gf));
    float so = 1.f / (1.f + expf(-go));
    float cc = sf * g_c2[b * DIM + o] + si * tanhf(gg);
    g_c2[b * DIM + o] = cc;
    g_h2[b * DIM + o] = so * tanhf(cc);
}

// ---------------- Set2Set attention: one block per graph ----------------
__global__ void attn_kernel() {
    int g = blockIdx.x;
    int s = g_goff[g], e = g_goff[g + 1];
    int lane = threadIdx.x & 31, w = threadIdx.x >> 5;
    __shared__ float q[DIM];
    __shared__ float red[4];
    __shared__ float sr[4][DIM];
    __shared__ float sd[4];
    if (threadIdx.x < DIM) q[threadIdx.x] = g_h2[g * DIM + threadIdx.x];
    __syncthreads();
    float mx = -INFINITY;
    for (int n = s + w; n < e; n += 4) {
        float v = g_x[n * DIM + lane] * q[lane];
#pragma unroll
        for (int off = 16; off; off >>= 1) v += __shfl_xor_sync(0xffffffffu, v, off);
        mx = fmaxf(mx, v);
    }
    if (lane == 0) red[w] = mx;
    __syncthreads();
    mx = fmaxf(fmaxf(red[0], red[1]), fmaxf(red[2], red[3]));
    float denom = 0.f, racc = 0.f;
    for (int n = s + w; n < e; n += 4) {
        float xo = g_x[n * DIM + lane];
        float v = xo * q[lane];
#pragma unroll
        for (int off = 16; off; off >>= 1) v += __shfl_xor_sync(0xffffffffu, v, off);
        float ex = __expf(v - mx);
        denom += ex;
        racc = fmaf(ex, xo, racc);
    }
    sr[w][lane] = racc;
    if (lane == 0) sd[w] = denom;
    __syncthreads();
    if (w == 0) {
        float r = sr[0][lane] + sr[1][lane] + sr[2][lane] + sr[3][lane];
        float d = sd[0] + sd[1] + sd[2] + sd[3];
        r = (d > 0.f) ? r / d : 0.f;
        g_qstar[g * 64 + lane] = q[lane];
        g_qstar[g * 64 + 32 + lane] = r;
    }
}

// ---------------- writeout: [pooled (2000x64), out (100000x32)] ----------------
__global__ void writeout_kernel(float* __restrict__ out) {
    int i = blockIdx.x * 256 + threadIdx.x;
    if (i >= NB * 64 + NN * DIM) return;
    out[i] = (i < NB * 64) ? g_qstar[i] : g_x[i - NB * 64];
}

// ---------------- launch ----------------
extern "C" void kernel_launch(void* const* d_in, const int* in_sizes, int n_in,
                              void* d_out, int out_size) {
    const float* nf        = (const float*)d_in[0];
    const float* ef        = (const float*)d_in[1];
    const float* lin0_w    = (const float*)d_in[2];
    const float* lin0_b    = (const float*)d_in[3];
    const float* nn_w1     = (const float*)d_in[4];
    const float* nn_b1     = (const float*)d_in[5];
    const float* nn_w2     = (const float*)d_in[6];
    const float* nn_b2     = (const float*)d_in[7];
    const float* conv_bias = (const float*)d_in[8];
    const float* gru_wih   = (const float*)d_in[9];
    const float* gru_whh   = (const float*)d_in[10];
    const float* gru_bih   = (const float*)d_in[11];
    const float* gru_bhh   = (const float*)d_in[12];
    const float* lstm_wih  = (const float*)d_in[13];
    const float* lstm_whh  = (const float*)d_in[14];
    const float* lstm_bih  = (const float*)d_in[15];
    const float* lstm_bhh  = (const float*)d_in[16];
    const int*   ei        = (const int*)d_in[17];
    const int*   gidx      = (const int*)d_in[18];

    static int smem_set = 0;
    if (!smem_set) {
        cudaFuncSetAttribute(gemm_fused_kernel, cudaFuncAttributeMaxDynamicSharedMemorySize,
                             SMEM_GEMM_TOTAL);
        smem_set = 1;
    }

    // conv_kernel is our 4th launch -> process launch #6 -> captured by ncu -s 5 -c 1
    prep_kernel<<<512, 256>>>(lin0_w, nn_w1, gru_wih, gru_whh, lstm_wih, lstm_whh, nn_w2, nn_b2);
    lin0_kernel<<<NN / 8, 256>>>(nf, lin0_b);          // also zeroes g_cnt / g_acc
    gemm_fused_kernel<<<MPAD / 128, 256, SMEM_GEMM_TOTAL>>>(ef, nn_b1);
    conv_kernel<<<NE / 8, 256>>>(ei);                  // iter 1 conv (profiled)
    deg_kernel<<<(NE + 255) / 256, 256>>>(ei);
    goff_kernel<<<8, 256>>>(gidx);
    gru_kernel<<<NN / 8, 256>>>(conv_bias, gru_bih, gru_bhh);

    for (int t = 0; t < 2; t++) {
        conv_kernel<<<NE / 8, 256>>>(ei);
        gru_kernel<<<NN / 8, 256>>>(conv_bias, gru_bih, gru_bhh);
    }

    zero_s2s_kernel<<<(NB * 2 * DIM + 255) / 256, 256>>>();
    for (int s = 0; s < 3; s++) {
        lstm_kernel<<<NB / 8, 256>>>(lstm_bih, lstm_bhh);
        attn_kernel<<<NB, 128>>>();
    }
    writeout_kernel<<<(NB * 64 + NN * DIM + 255) / 256, 256>>>((float*)d_out);
}

// round 12
// speedup vs baseline: 1.0616x; 1.0616x over previous
#include <cuda_runtime.h>
#include <cuda_fp16.h>
#include <math.h>
#include <stdint.h>

#define NN   100000
#define NE   250000
#define NB   2000
#define FIN  75
#define DIM  32
#define HID  128
#define NOUT 1024           // DIM*DIM
#define MPAD 250112         // 1954 * 128

// ---------------- scratch (static __device__, no allocation) ----------------
__device__ __align__(16) __half g_ewb[(size_t)MPAD * NOUT];  // edge weights fp16, [o][i] per edge
__device__ __align__(16) __half g_w2b[NOUT * HID];           // W2 fp16, column-permuted (c' = o*32+i)
__device__ float g_b2p[NOUT];                                // b2 permuted
__device__ float g_x[NN * DIM];                 // node state
__device__ float g_acc[NN * DIM];               // conv scatter accumulator
__device__ int   g_cnt[NN];                     // in-degree
__device__ int   g_goff[NB + 1];                // graph offsets (graph_index is sorted)
__device__ float g_h2[NB * DIM];                // set2set LSTM h
__device__ float g_c2[NB * DIM];                // set2set LSTM c
__device__ float g_qstar[NB * 2 * DIM];         // set2set q_star
// transposed weights
__device__ float g_w0T[FIN * DIM];
__device__ float g_w1T[11 * HID];
__device__ float g_wihT[DIM * 96];
__device__ float g_whhT[DIM * 96];
__device__ float g_lwihT[64 * 128];
__device__ float g_lwhhT[DIM * 128];

__device__ __forceinline__ uint32_t smem_u32(const void* p) {
    uint32_t a;
    asm("{ .reg .u64 t; cvta.to.shared.u64 t, %1; cvt.u32.u64 %0, t; }" : "=r"(a) : "l"(p));
    return a;
}

// ---------------- prep: transposes + fp16 W2 with column permutation ----------------
__global__ void prep_kernel(const float* __restrict__ w0, const float* __restrict__ w1,
                            const float* __restrict__ gwih, const float* __restrict__ gwhh,
                            const float* __restrict__ lwih, const float* __restrict__ lwhh,
                            const float* __restrict__ w2, const float* __restrict__ b2) {
    int t = blockIdx.x * 256 + threadIdx.x;
    if (t < FIN * DIM) { int i = t / DIM, o = t % DIM; g_w0T[t] = w0[o * FIN + i]; }
    if (t < 11 * HID)  { int i = t / HID, j = t % HID; g_w1T[t] = w1[j * 11 + i]; }
    if (t < DIM * 96)  { int i = t / 96,  r = t % 96;  g_wihT[t] = gwih[r * DIM + i]; g_whhT[t] = gwhh[r * DIM + i]; }
    if (t < 64 * 128)  { int i = t / 128, r = t % 128; g_lwihT[t] = lwih[r * 64 + i]; }
    if (t < DIM * 128) { int i = t / 128, r = t % 128; g_lwhhT[t] = lwhh[r * DIM + i]; }
    if (t < NOUT) { int corig = (t & 31) * 32 + (t >> 5); g_b2p[t] = b2[corig]; }
    if (t < NOUT * HID) {
        int cp = t / HID, k = t % HID;
        int corig = (cp & 31) * 32 + (cp >> 5);      // cp = o*32+i holds original column i*32+o
        g_w2b[t] = __float2half(w2[corig * HID + k]);
    }
}

__global__ void deg_kernel(const int* __restrict__ ei) {
    int e = blockIdx.x * 256 + threadIdx.x;
    if (e < NE) atomicAdd(&g_cnt[ei[NE + e]], 1);
}

__global__ void goff_kernel(const int* __restrict__ gidx) {
    int g = blockIdx.x * 256 + threadIdx.x;
    if (g > NB) return;
    int lo = 0, hi = NN;
    while (lo < hi) { int mid = (lo + hi) >> 1; if (gidx[mid] < g) lo = mid + 1; else hi = mid; }
    g_goff[g] = lo;
}

// ---------------- lin0: 64 nodes/block, 8 nodes/warp (weight loads amortized) ----------------
__global__ void __launch_bounds__(256) lin0_kernel(const float* __restrict__ nf,
                                                   const float* __restrict__ b) {
    __shared__ float sf[64][FIN + 1];
    int tid = threadIdx.x;
    int base = blockIdx.x * 64;
    for (int idx = tid; idx < 64 * FIN; idx += 256) {
        int n = idx / FIN, i = idx % FIN;
        int node = base + n;
        sf[n][i] = (node < NN) ? nf[(size_t)node * FIN + i] : 0.f;
    }
    __syncthreads();
    int warp = tid >> 5, o = tid & 31;
    int n0 = warp * 8;
    float acc[8];
    float bo = b[o];
#pragma unroll
    for (int n = 0; n < 8; n++) acc[n] = bo;
    for (int i = 0; i < FIN; i++) {
        float w = g_w0T[i * DIM + o];
#pragma unroll
        for (int n = 0; n < 8; n++) acc[n] = fmaf(sf[n0 + n][i], w, acc[n]);
    }
#pragma unroll
    for (int n = 0; n < 8; n++) {
        int node = base + n0 + n;
        if (node < NN) {
            g_x[node * DIM + o] = fmaxf(acc[n], 0.f);
            g_acc[node * DIM + o] = 0.f;
            if (o == 0) g_cnt[node] = 0;
        }
    }
}

// ---- fused GEMM (R9 version): per CTA of 128 edges; hw built in-smem, loop over 8 N-slabs ----
#define SM_A     0
#define SM_B     32768
#define SM_CSTG  65536
#define SM_SEF   65536           // 128 x 12 floats
#define SM_W1T   (65536 + 6144)
#define SM_B1    (65536 + 6144 + 5632)
#define SM_BIAS  100352          // 1024 floats
#define SMEM_GEMM_TOTAL 104448
#define CSTRIDE 272

__device__ __forceinline__ void mma_fp16(float* c, const uint32_t* a, uint32_t b0, uint32_t b1) {
    asm volatile(
        "mma.sync.aligned.m16n8k16.row.col.f32.f16.f16.f32 "
        "{%0,%1,%2,%3}, {%4,%5,%6,%7}, {%8,%9}, {%0,%1,%2,%3};"
        : "+f"(c[0]), "+f"(c[1]), "+f"(c[2]), "+f"(c[3])
        : "r"(a[0]), "r"(a[1]), "r"(a[2]), "r"(a[3]), "r"(b0), "r"(b1));
}

__global__ void __launch_bounds__(256) gemm_fused_kernel(const float* __restrict__ ef,
                                                         const float* __restrict__ b1) {
    extern __shared__ __align__(16) char smem[];
    uint32_t sbase = smem_u32(smem);
    float* sef   = (float*)(smem + SM_SEF);
    float* sw1t  = (float*)(smem + SM_W1T);
    float* sb1   = (float*)(smem + SM_B1);
    float* sbias = (float*)(smem + SM_BIAS);
    int tid = threadIdx.x, lane = tid & 31, wid = tid >> 5;
    int e0 = blockIdx.x * 128;

    for (int idx = tid; idx < 128 * 11; idx += 256) {
        int r = idx / 11, i = idx % 11;
        int e = e0 + r;
        sef[r * 12 + i] = (e < NE) ? ef[(size_t)e * 11 + i] : 0.f;
    }
    for (int idx = tid; idx < 11 * HID; idx += 256) sw1t[idx] = g_w1T[idx];
    if (tid < 128) sb1[tid] = b1[tid];
#pragma unroll
    for (int l = 0; l < 4; l++) sbias[tid + l * 256] = g_b2p[tid + l * 256];
    __syncthreads();

#pragma unroll
    for (int ci = 0; ci < 8; ci++) {
        int cidx = tid + ci * 256;
        int row = cidx >> 4, c = cidx & 15;
        int k0 = c * 8;
        float v[8];
#pragma unroll
        for (int j = 0; j < 8; j++) v[j] = sb1[k0 + j];
#pragma unroll
        for (int i = 0; i < 11; i++) {
            float e_ = sef[row * 12 + i];
#pragma unroll
            for (int j = 0; j < 8; j++) v[j] = fmaf(e_, sw1t[i * HID + k0 + j], v[j]);
        }
        uint32_t p[4];
#pragma unroll
        for (int j = 0; j < 4; j++) {
            __half2 h = __floats2half2_rn(fmaxf(v[2 * j], 0.f), fmaxf(v[2 * j + 1], 0.f));
            p[j] = *(uint32_t*)&h;
        }
        int cs = (c & 8) | ((c ^ row) & 7);
        *(uint4*)(smem + SM_A + row * 256 + cs * 16) = make_uint4(p[0], p[1], p[2], p[3]);
    }
    __syncthreads();

    int wm = (wid & 3) * 32;
    int wn = (wid >> 2) * 64;

    for (int nb = 0; nb < 8; nb++) {
        const uint4* gB = (const uint4*)(g_w2b + (size_t)(nb * 128) * HID);
#pragma unroll
        for (int it = 0; it < 8; it++) {
            int idx = tid + it * 256;
            int row = idx >> 4, c = idx & 15;
            uint4 v = gB[idx];
            int cs = (c & 8) | ((c ^ row) & 7);
            *(uint4*)(smem + SM_B + row * 256 + cs * 16) = v;
        }
        __syncthreads();

        float acc[2][8][4];
#pragma unroll
        for (int mb = 0; mb < 2; mb++)
#pragma unroll
            for (int nbb = 0; nbb < 8; nbb++)
#pragma unroll
                for (int q = 0; q < 4; q++) acc[mb][nbb][q] = 0.f;

#pragma unroll
        for (int ks = 0; ks < 8; ks++) {
            int ck0 = ks * 2;
            uint32_t a[2][4], b[4][4];
#pragma unroll
            for (int mb = 0; mb < 2; mb++) {
                int row = wm + mb * 16 + (lane & 7) + ((lane >> 3) & 1) * 8;
                int ck = ck0 + (lane >> 4);
                int cs = (ck & 8) | ((ck ^ row) & 7);
                uint32_t addr = sbase + SM_A + row * 256 + cs * 16;
                asm volatile("ldmatrix.sync.aligned.m8n8.x4.shared.b16 {%0,%1,%2,%3}, [%4];"
                             : "=r"(a[mb][0]), "=r"(a[mb][1]), "=r"(a[mb][2]), "=r"(a[mb][3])
                             : "r"(addr));
            }
#pragma unroll
            for (int nb4 = 0; nb4 < 4; nb4++) {
                int t = lane >> 3, r = lane & 7;
                int n = wn + nb4 * 16 + r + (t >> 1) * 8;
                int ck = ck0 + (t & 1);
                int cs = (ck & 8) | ((ck ^ n) & 7);
                uint32_t addr = sbase + SM_B + n * 256 + cs * 16;
                asm volatile("ldmatrix.sync.aligned.m8n8.x4.shared.b16 {%0,%1,%2,%3}, [%4];"
                             : "=r"(b[nb4][0]), "=r"(b[nb4][1]), "=r"(b[nb4][2]), "=r"(b[nb4][3])
                             : "r"(addr));
            }
#pragma unroll
            for (int mb = 0; mb < 2; mb++)
#pragma unroll
                for (int nbb = 0; nbb < 8; nbb++)
                    mma_fp16(acc[mb][nbb], a[mb], b[nbb >> 1][(nbb & 1) * 2], b[nbb >> 1][(nbb & 1) * 2 + 1]);
        }
        __syncthreads();

        int g = lane >> 2, tg = lane & 3;
#pragma unroll
        for (int mb = 0; mb < 2; mb++)
#pragma unroll
            for (int nbb = 0; nbb < 8; nbb++) {
                int rowl = wm + mb * 16 + g;
                int nl = wn + nbb * 8 + tg * 2;
                float bb0 = sbias[nb * 128 + nl], bb1 = sbias[nb * 128 + nl + 1];
                float* c = acc[mb][nbb];
                __half2 p0 = __floats2half2_rn(c[0] + bb0, c[1] + bb1);
                __half2 p1 = __floats2half2_rn(c[2] + bb0, c[3] + bb1);
                *(uint32_t*)(smem + SM_CSTG + rowl * CSTRIDE + nl * 2) = *(uint32_t*)&p0;
                *(uint32_t*)(smem + SM_CSTG + (rowl + 8) * CSTRIDE + nl * 2) = *(uint32_t*)&p1;
            }
        __syncthreads();

        __half* dst = g_ewb + (size_t)e0 * NOUT + nb * 128;
#pragma unroll
        for (int it = 0; it < 8; it++) {
            int idx = tid + it * 256;
            int row = idx >> 4, c = idx & 15;
            uint4 v = *(const uint4*)(smem + SM_CSTG + row * CSTRIDE + c * 16);
            *(uint4*)(dst + (size_t)row * NOUT + c * 8) = v;
        }
        __syncthreads();
    }
}

// ---------------- NNConv: warp per edge, lane = output channel, [o][i] vectorized loads ----------------
__global__ void conv_kernel(const int* __restrict__ ei) {
    int e = blockIdx.x * 8 + (threadIdx.x >> 5);
    if (e >= NE) return;
    int o = threadIdx.x & 31;
    int src = ei[e];
    int dst = ei[NE + e];
    float xv = g_x[src * DIM + o];
    const uint4* w = (const uint4*)(g_ewb + (size_t)e * NOUT + o * 32);
    uint4 w0 = w[0], w1 = w[1], w2 = w[2], w3 = w[3];
    uint32_t ws[16] = {w0.x, w0.y, w0.z, w0.w, w1.x, w1.y, w1.z, w1.w,
                       w2.x, w2.y, w2.z, w2.w, w3.x, w3.y, w3.z, w3.w};
    float acc = 0.f;
#pragma unroll
    for (int i = 0; i < 16; i++) {
        float2 wp = __half22float2(*(__half2*)&ws[i]);
        float x0 = __shfl_sync(0xffffffffu, xv, 2 * i);
        float x1 = __shfl_sync(0xffffffffu, xv, 2 * i + 1);
        acc = fmaf(x0, wp.x, fmaf(x1, wp.y, acc));
    }
    atomicAdd(&g_acc[dst * DIM + o], acc);
}

// ---------------- GRU: 64 nodes/block, 8 nodes/warp (weight loads amortized 8x) ----------------
__global__ void __launch_bounds__(256) gru_kernel(const float* __restrict__ cbias,
                                                  const float* __restrict__ bih,
                                                  const float* __restrict__ bhh) {
    __shared__ float sm[64][DIM], sh[64][DIM];
    int tid = threadIdx.x;
    int base = blockIdx.x * 64;
#pragma unroll
    for (int l = 0; l < 8; l++) {
        int idx = tid + l * 256;
        int n = idx >> 5, o = idx & 31;
        int node = base + n;
        if (node < NN) {
            int c = g_cnt[node]; if (c < 1) c = 1;
            sm[n][o] = fmaxf(g_acc[node * DIM + o] / (float)c + cbias[o], 0.f);
            sh[n][o] = g_x[node * DIM + o];
            g_acc[node * DIM + o] = 0.f;   // ready for next conv iteration
        }
    }
    __syncthreads();
    int warp = tid >> 5, o = tid & 31;
    int n0 = warp * 8;
    float gir[8], giz[8], gin[8], ghr[8], ghz[8], ghn[8];
    float b0 = bih[o], b1 = bih[DIM + o], b2 = bih[2 * DIM + o];
    float c0 = bhh[o], c1 = bhh[DIM + o], c2 = bhh[2 * DIM + o];
#pragma unroll
    for (int n = 0; n < 8; n++) {
        gir[n] = b0; giz[n] = b1; gin[n] = b2;
        ghr[n] = c0; ghz[n] = c1; ghn[n] = c2;
    }
#pragma unroll 4
    for (int i = 0; i < DIM; i++) {
        float wr = g_wihT[i * 96 + o], wz = g_wihT[i * 96 + DIM + o], wn_ = g_wihT[i * 96 + 2 * DIM + o];
        float vr = g_whhT[i * 96 + o], vz = g_whhT[i * 96 + DIM + o], vn = g_whhT[i * 96 + 2 * DIM + o];
#pragma unroll
        for (int n = 0; n < 8; n++) {
            float mi = sm[n0 + n][i], hi = sh[n0 + n][i];
            gir[n] = fmaf(mi, wr, gir[n]);
            giz[n] = fmaf(mi, wz, giz[n]);
            gin[n] = fmaf(mi, wn_, gin[n]);
            ghr[n] = fmaf(hi, vr, ghr[n]);
            ghz[n] = fmaf(hi, vz, ghz[n]);
            ghn[n] = fmaf(hi, vn, ghn[n]);
        }
    }
#pragma unroll
    for (int n = 0; n < 8; n++) {
        int node = base + n0 + n;
        if (node < NN) {
            float r = 1.f / (1.f + expf(-(gir[n] + ghr[n])));
            float z = 1.f / (1.f + expf(-(giz[n] + ghz[n])));
            float nv = tanhf(gin[n] + r * ghn[n]);
            g_x[node * DIM + o] = (1.f - z) * nv + z * sh[n0 + n][o];
        }
    }
}

__global__ void zero_s2s_kernel() {
    int i = blockIdx.x * 256 + threadIdx.x;
    if (i < NB * DIM) { g_h2[i] = 0.f; g_c2[i] = 0.f; }
    if (i < NB * 2 * DIM) g_qstar[i] = 0.f;
}

// ---------------- Set2Set LSTM cell ----------------
__global__ void lstm_kernel(const float* __restrict__ bih, const float* __restrict__ bhh) {
    int warp = threadIdx.x >> 5;
    int b = blockIdx.x * 8 + warp;
    int o = threadIdx.x & 31;
    __shared__ float sq[8][64], shh[8][DIM];
    if (b < NB) {
        sq[warp][o]      = g_qstar[b * 64 + o];
        sq[warp][32 + o] = g_qstar[b * 64 + 32 + o];
        shh[warp][o]     = g_h2[b * DIM + o];
    }
    __syncthreads();
    if (b >= NB) return;
    float gi = bih[o] + bhh[o];
    float gf = bih[32 + o] + bhh[32 + o];
    float gg = bih[64 + o] + bhh[64 + o];
    float go = bih[96 + o] + bhh[96 + o];
#pragma unroll
    for (int i = 0; i < 64; i++) {
        float v = sq[warp][i];
        gi = fmaf(v, g_lwihT[i * 128 + o], gi);
        gf = fmaf(v, g_lwihT[i * 128 + 32 + o], gf);
        gg = fmaf(v, g_lwihT[i * 128 + 64 + o], gg);
        go = fmaf(v, g_lwihT[i * 128 + 96 + o], go);
    }
#pragma unroll
    for (int i = 0; i < DIM; i++) {
        float v = shh[warp][i];
        gi = fmaf(v, g_lwhhT[i * 128 + o], gi);
        gf = fmaf(v, g_lwhhT[i * 128 + 32 + o], gf);
        gg = fmaf(v, g_lwhhT[i * 128 + 64 + o], gg);
        go = fmaf(v, g_lwhhT[i * 128 + 96 + o], go);
    }
    float si = 1.f / (1.f + expf(-gi));
    float sf = 1.f / (1.f + expf(-gf));
    float so = 1.f / (1.f + expf(-go));
    float cc = sf * g_c2[b * DIM + o] + si * tanhf(gg);
    g_c2[b * DIM + o] = cc;
    g_h2[b * DIM + o] = so * tanhf(cc);
}

// ---------------- Set2Set attention: one block per graph ----------------
__global__ void attn_kernel() {
    int g = blockIdx.x;
    int s = g_goff[g], e = g_goff[g + 1];
    int lane = threadIdx.x & 31, w = threadIdx.x >> 5;
    __shared__ float q[DIM];
    __shared__ float red[4];
    __shared__ float sr[4][DIM];
    __shared__ float sd[4];
    if (threadIdx.x < DIM) q[threadIdx.x] = g_h2[g * DIM + threadIdx.x];
    __syncthreads();
    float mx = -INFINITY;
    for (int n = s + w; n < e; n += 4) {
        float v = g_x[n * DIM + lane] * q[lane];
#pragma unroll
        for (int off = 16; off; off >>= 1) v += __shfl_xor_sync(0xffffffffu, v, off);
        mx = fmaxf(mx, v);
    }
    if (lane == 0) red[w] = mx;
    __syncthreads();
    mx = fmaxf(fmaxf(red[0], red[1]), fmaxf(red[2], red[3]));
    float denom = 0.f, racc = 0.f;
    for (int n = s + w; n < e; n += 4) {
        float xo = g_x[n * DIM + lane];
        float v = xo * q[lane];
#pragma unroll
        for (int off = 16; off; off >>= 1) v += __shfl_xor_sync(0xffffffffu, v, off);
        float ex = __expf(v - mx);
        denom += ex;
        racc = fmaf(ex, xo, racc);
    }
    sr[w][lane] = racc;
    if (lane == 0) sd[w] = denom;
    __syncthreads();
    if (w == 0) {
        float r = sr[0][lane] + sr[1][lane] + sr[2][lane] + sr[3][lane];
        float d = sd[0] + sd[1] + sd[2] + sd[3];
        r = (d > 0.f) ? r / d : 0.f;
        g_qstar[g * 64 + lane] = q[lane];
        g_qstar[g * 64 + 32 + lane] = r;
    }
}

// ---------------- writeout: [pooled (2000x64), out (100000x32)] ----------------
__global__ void writeout_kernel(float* __restrict__ out) {
    int i = blockIdx.x * 256 + threadIdx.x;
    if (i >= NB * 64 + NN * DIM) return;
    out[i] = (i < NB * 64) ? g_qstar[i] : g_x[i - NB * 64];
}

// ---------------- launch ----------------
extern "C" void kernel_launch(void* const* d_in, const int* in_sizes, int n_in,
                              void* d_out, int out_size) {
    const float* nf        = (const float*)d_in[0];
    const float* ef        = (const float*)d_in[1];
    const float* lin0_w    = (const float*)d_in[2];
    const float* lin0_b    = (const float*)d_in[3];
    const float* nn_w1     = (const float*)d_in[4];
    const float* nn_b1     = (const float*)d_in[5];
    const float* nn_w2     = (const float*)d_in[6];
    const float* nn_b2     = (const float*)d_in[7];
    const float* conv_bias = (const float*)d_in[8];
    const float* gru_wih   = (const float*)d_in[9];
    const float* gru_whh   = (const float*)d_in[10];
    const float* gru_bih   = (const float*)d_in[11];
    const float* gru_bhh   = (const float*)d_in[12];
    const float* lstm_wih  = (const float*)d_in[13];
    const float* lstm_whh  = (const float*)d_in[14];
    const float* lstm_bih  = (const float*)d_in[15];
    const float* lstm_bhh  = (const float*)d_in[16];
    const int*   ei        = (const int*)d_in[17];
    const int*   gidx      = (const int*)d_in[18];

    static int smem_set = 0;
    if (!smem_set) {
        cudaFuncSetAttribute(gemm_fused_kernel, cudaFuncAttributeMaxDynamicSharedMemorySize,
                             SMEM_GEMM_TOTAL);
        smem_set = 1;
    }

    // gemm is our 4th launch -> captured by ncu (-s 5 -c 1, after ~2 harness launches)
    prep_kernel<<<512, 256>>>(lin0_w, nn_w1, gru_wih, gru_whh, lstm_wih, lstm_whh, nn_w2, nn_b2);
    lin0_kernel<<<(NN + 63) / 64, 256>>>(nf, lin0_b);  // also zeroes g_cnt / g_acc
    deg_kernel<<<(NE + 255) / 256, 256>>>(ei);
    gemm_fused_kernel<<<MPAD / 128, 256, SMEM_GEMM_TOTAL>>>(ef, nn_b1);
    goff_kernel<<<8, 256>>>(gidx);

    for (int t = 0; t < 3; t++) {
        conv_kernel<<<NE / 8, 256>>>(ei);
        gru_kernel<<<(NN + 63) / 64, 256>>>(conv_bias, gru_bih, gru_bhh);
    }

    zero_s2s_kernel<<<(NB * 2 * DIM + 255) / 256, 256>>>();
    for (int s = 0; s < 3; s++) {
        lstm_kernel<<<NB / 8, 256>>>(lstm_bih, lstm_bhh);
        attn_kernel<<<NB, 128>>>();
    }
    writeout_kernel<<<(NB * 64 + NN * DIM + 255) / 256, 256>>>((float*)d_out);
}

// round 13
// speedup vs baseline: 1.1014x; 1.0375x over previous
#include <cuda_runtime.h>
#include <cuda_fp16.h>
#include <math.h>
#include <stdint.h>

#define NN   100000
#define NE   250000
#define NB   2000
#define FIN  75
#define DIM  32
#define HID  128
#define NOUT 1024           // DIM*DIM
#define MPAD 250112         // 1954 * 128

// ---------------- scratch (static __device__, no allocation) ----------------
__device__ __align__(16) __half g_ewb[(size_t)MPAD * NOUT];  // edge weights fp16, [o][i] per edge
__device__ __align__(16) __half g_w2b[NOUT * HID];           // W2 fp16, column-permuted (c' = o*32+i)
__device__ float g_b2p[NOUT];                                // b2 permuted
__device__ float g_x[NN * DIM];                 // node state
__device__ float g_acc[NN * DIM];               // conv scatter accumulator
__device__ int   g_cnt[NN];                     // in-degree
// transposed weights
__device__ float g_w0T[FIN * DIM];
__device__ float g_w1T[11 * HID];
__device__ float g_wihT[DIM * 96];
__device__ float g_whhT[DIM * 96];
__device__ float g_lwihT[64 * 128];
__device__ float g_lwhhT[DIM * 128];

__device__ __forceinline__ uint32_t smem_u32(const void* p) {
    uint32_t a;
    asm("{ .reg .u64 t; cvta.to.shared.u64 t, %1; cvt.u32.u64 %0, t; }" : "=r"(a) : "l"(p));
    return a;
}

// ---------------- prep: transposes + fp16 W2 with column permutation ----------------
__global__ void prep_kernel(const float* __restrict__ w0, const float* __restrict__ w1,
                            const float* __restrict__ gwih, const float* __restrict__ gwhh,
                            const float* __restrict__ lwih, const float* __restrict__ lwhh,
                            const float* __restrict__ w2, const float* __restrict__ b2) {
    int t = blockIdx.x * 256 + threadIdx.x;
    if (t < FIN * DIM) { int i = t / DIM, o = t % DIM; g_w0T[t] = w0[o * FIN + i]; }
    if (t < 11 * HID)  { int i = t / HID, j = t % HID; g_w1T[t] = w1[j * 11 + i]; }
    if (t < DIM * 96)  { int i = t / 96,  r = t % 96;  g_wihT[t] = gwih[r * DIM + i]; g_whhT[t] = gwhh[r * DIM + i]; }
    if (t < 64 * 128)  { int i = t / 128, r = t % 128; g_lwihT[t] = lwih[r * 64 + i]; }
    if (t < DIM * 128) { int i = t / 128, r = t % 128; g_lwhhT[t] = lwhh[r * DIM + i]; }
    if (t < NOUT) { int corig = (t & 31) * 32 + (t >> 5); g_b2p[t] = b2[corig]; }
    if (t < NOUT * HID) {
        int cp = t / HID, k = t % HID;
        int corig = (cp & 31) * 32 + (cp >> 5);      // cp = o*32+i holds original column i*32+o
        g_w2b[t] = __float2half(w2[corig * HID + k]);
    }
}

__global__ void deg_kernel(const int* __restrict__ ei) {
    int e = blockIdx.x * 256 + threadIdx.x;
    if (e < NE) atomicAdd(&g_cnt[ei[NE + e]], 1);
}

// ---------------- lin0: 64 nodes/block, 8 nodes/warp; also zeroes g_cnt / g_acc ----------------
__global__ void __launch_bounds__(256) lin0_kernel(const float* __restrict__ nf,
                                                   const float* __restrict__ b) {
    __shared__ float sf[64][FIN + 1];
    int tid = threadIdx.x;
    int base = blockIdx.x * 64;
    for (int idx = tid; idx < 64 * FIN; idx += 256) {
        int n = idx / FIN, i = idx % FIN;
        int node = base + n;
        sf[n][i] = (node < NN) ? nf[(size_t)node * FIN + i] : 0.f;
    }
    __syncthreads();
    int warp = tid >> 5, o = tid & 31;
    int n0 = warp * 8;
    float acc[8];
    float bo = b[o];
#pragma unroll
    for (int n = 0; n < 8; n++) acc[n] = bo;
    for (int i = 0; i < FIN; i++) {
        float w = g_w0T[i * DIM + o];
#pragma unroll
        for (int n = 0; n < 8; n++) acc[n] = fmaf(sf[n0 + n][i], w, acc[n]);
    }
#pragma unroll
    for (int n = 0; n < 8; n++) {
        int node = base + n0 + n;
        if (node < NN) {
            g_x[node * DIM + o] = fmaxf(acc[n], 0.f);
            g_acc[node * DIM + o] = 0.f;
            if (o == 0) g_cnt[node] = 0;
        }
    }
}

// ---- fused GEMM: per CTA of 128 edges; hw built in-smem, loop over 8 N-slabs ----
#define SM_A     0
#define SM_B     32768
#define SM_CSTG  65536
#define SM_SEF   65536           // 128 x 12 floats
#define SM_W1T   (65536 + 6144)
#define SM_B1    (65536 + 6144 + 5632)
#define SM_BIAS  100352          // 1024 floats
#define SMEM_GEMM_TOTAL 104448
#define CSTRIDE 272

__device__ __forceinline__ void mma_fp16(float* c, const uint32_t* a, uint32_t b0, uint32_t b1) {
    asm volatile(
        "mma.sync.aligned.m16n8k16.row.col.f32.f16.f16.f32 "
        "{%0,%1,%2,%3}, {%4,%5,%6,%7}, {%8,%9}, {%0,%1,%2,%3};"
        : "+f"(c[0]), "+f"(c[1]), "+f"(c[2]), "+f"(c[3])
        : "r"(a[0]), "r"(a[1]), "r"(a[2]), "r"(a[3]), "r"(b0), "r"(b1));
}

__global__ void __launch_bounds__(256) gemm_fused_kernel(const float* __restrict__ ef,
                                                         const float* __restrict__ b1) {
    extern __shared__ __align__(16) char smem[];
    uint32_t sbase = smem_u32(smem);
    float* sef   = (float*)(smem + SM_SEF);
    float* sw1t  = (float*)(smem + SM_W1T);
    float* sb1   = (float*)(smem + SM_B1);
    float* sbias = (float*)(smem + SM_BIAS);
    int tid = threadIdx.x, lane = tid & 31, wid = tid >> 5;
    int e0 = blockIdx.x * 128;

    for (int idx = tid; idx < 128 * 11; idx += 256) {
        int r = idx / 11, i = idx % 11;
        int e = e0 + r;
        sef[r * 12 + i] = (e < NE) ? ef[(size_t)e * 11 + i] : 0.f;
    }
    for (int idx = tid; idx < 11 * HID; idx += 256) sw1t[idx] = g_w1T[idx];
    if (tid < 128) sb1[tid] = b1[tid];
#pragma unroll
    for (int l = 0; l < 4; l++) sbias[tid + l * 256] = g_b2p[tid + l * 256];
    __syncthreads();

#pragma unroll
    for (int ci = 0; ci < 8; ci++) {
        int cidx = tid + ci * 256;
        int row = cidx >> 4, c = cidx & 15;
        int k0 = c * 8;
        float v[8];
#pragma unroll
        for (int j = 0; j < 8; j++) v[j] = sb1[k0 + j];
#pragma unroll
        for (int i = 0; i < 11; i++) {
            float e_ = sef[row * 12 + i];
#pragma unroll
            for (int j = 0; j < 8; j++) v[j] = fmaf(e_, sw1t[i * HID + k0 + j], v[j]);
        }
        uint32_t p[4];
#pragma unroll
        for (int j = 0; j < 4; j++) {
            __half2 h = __floats2half2_rn(fmaxf(v[2 * j], 0.f), fmaxf(v[2 * j + 1], 0.f));
            p[j] = *(uint32_t*)&h;
        }
        int cs = (c & 8) | ((c ^ row) & 7);
        *(uint4*)(smem + SM_A + row * 256 + cs * 16) = make_uint4(p[0], p[1], p[2], p[3]);
    }
    __syncthreads();

    int wm = (wid & 3) * 32;
    int wn = (wid >> 2) * 64;

    for (int nb = 0; nb < 8; nb++) {
        const uint4* gB = (const uint4*)(g_w2b + (size_t)(nb * 128) * HID);
#pragma unroll
        for (int it = 0; it < 8; it++) {
            int idx = tid + it * 256;
            int row = idx >> 4, c = idx & 15;
            uint4 v = gB[idx];
            int cs = (c & 8) | ((c ^ row) & 7);
            *(uint4*)(smem + SM_B + row * 256 + cs * 16) = v;
        }
        __syncthreads();

        float acc[2][8][4];
#pragma unroll
        for (int mb = 0; mb < 2; mb++)
#pragma unroll
            for (int nbb = 0; nbb < 8; nbb++)
#pragma unroll
                for (int q = 0; q < 4; q++) acc[mb][nbb][q] = 0.f;

#pragma unroll
        for (int ks = 0; ks < 8; ks++) {
            int ck0 = ks * 2;
            uint32_t a[2][4], b[4][4];
#pragma unroll
            for (int mb = 0; mb < 2; mb++) {
                int row = wm + mb * 16 + (lane & 7) + ((lane >> 3) & 1) * 8;
                int ck = ck0 + (lane >> 4);
                int cs = (ck & 8) | ((ck ^ row) & 7);
                uint32_t addr = sbase + SM_A + row * 256 + cs * 16;
                asm volatile("ldmatrix.sync.aligned.m8n8.x4.shared.b16 {%0,%1,%2,%3}, [%4];"
                             : "=r"(a[mb][0]), "=r"(a[mb][1]), "=r"(a[mb][2]), "=r"(a[mb][3])
                             : "r"(addr));
            }
#pragma unroll
            for (int nb4 = 0; nb4 < 4; nb4++) {
                int t = lane >> 3, r = lane & 7;
                int n = wn + nb4 * 16 + r + (t >> 1) * 8;
                int ck = ck0 + (t & 1);
                int cs = (ck & 8) | ((ck ^ n) & 7);
                uint32_t addr = sbase + SM_B + n * 256 + cs * 16;
                asm volatile("ldmatrix.sync.aligned.m8n8.x4.shared.b16 {%0,%1,%2,%3}, [%4];"
                             : "=r"(b[nb4][0]), "=r"(b[nb4][1]), "=r"(b[nb4][2]), "=r"(b[nb4][3])
                             : "r"(addr));
            }
#pragma unroll
            for (int mb = 0; mb < 2; mb++)
#pragma unroll
                for (int nbb = 0; nbb < 8; nbb++)
                    mma_fp16(acc[mb][nbb], a[mb], b[nbb >> 1][(nbb & 1) * 2], b[nbb >> 1][(nbb & 1) * 2 + 1]);
        }
        __syncthreads();

        int g = lane >> 2, tg = lane & 3;
#pragma unroll
        for (int mb = 0; mb < 2; mb++)
#pragma unroll
            for (int nbb = 0; nbb < 8; nbb++) {
                int rowl = wm + mb * 16 + g;
                int nl = wn + nbb * 8 + tg * 2;
                float bb0 = sbias[nb * 128 + nl], bb1 = sbias[nb * 128 + nl + 1];
                float* c = acc[mb][nbb];
                __half2 p0 = __floats2half2_rn(c[0] + bb0, c[1] + bb1);
                __half2 p1 = __floats2half2_rn(c[2] + bb0, c[3] + bb1);
                *(uint32_t*)(smem + SM_CSTG + rowl * CSTRIDE + nl * 2) = *(uint32_t*)&p0;
                *(uint32_t*)(smem + SM_CSTG + (rowl + 8) * CSTRIDE + nl * 2) = *(uint32_t*)&p1;
            }
        __syncthreads();

        __half* dst = g_ewb + (size_t)e0 * NOUT + nb * 128;
#pragma unroll
        for (int it = 0; it < 8; it++) {
            int idx = tid + it * 256;
            int row = idx >> 4, c = idx & 15;
            uint4 v = *(const uint4*)(smem + SM_CSTG + row * CSTRIDE + c * 16);
            *(uint4*)(dst + (size_t)row * NOUT + c * 8) = v;
        }
        __syncthreads();
    }
}

// ---------------- NNConv: warp per edge, lane = output channel, [o][i] vectorized loads ----------------
__global__ void conv_kernel(const int* __restrict__ ei) {
    int e = blockIdx.x * 8 + (threadIdx.x >> 5);
    if (e >= NE) return;
    int o = threadIdx.x & 31;
    int src = ei[e];
    int dst = ei[NE + e];
    float xv = g_x[src * DIM + o];
    const uint4* w = (const uint4*)(g_ewb + (size_t)e * NOUT + o * 32);
    uint4 w0 = w[0], w1 = w[1], w2 = w[2], w3 = w[3];
    uint32_t ws[16] = {w0.x, w0.y, w0.z, w0.w, w1.x, w1.y, w1.z, w1.w,
                       w2.x, w2.y, w2.z, w2.w, w3.x, w3.y, w3.z, w3.w};
    float acc = 0.f;
#pragma unroll
    for (int i = 0; i < 16; i++) {
        float2 wp = __half22float2(*(__half2*)&ws[i]);
        float x0 = __shfl_sync(0xffffffffu, xv, 2 * i);
        float x1 = __shfl_sync(0xffffffffu, xv, 2 * i + 1);
        acc = fmaf(x0, wp.x, fmaf(x1, wp.y, acc));
    }
    atomicAdd(&g_acc[dst * DIM + o], acc);
}

// ---------------- GRU: 64 nodes/block, 8 nodes/warp; zeroes g_acc after read ----------------
__global__ void __launch_bounds__(256) gru_kernel(const float* __restrict__ cbias,
                                                  const float* __restrict__ bih,
                                                  const float* __restrict__ bhh) {
    __shared__ float sm[64][DIM], sh[64][DIM];
    int tid = threadIdx.x;
    int base = blockIdx.x * 64;
#pragma unroll
    for (int l = 0; l < 8; l++) {
        int idx = tid + l * 256;
        int n = idx >> 5, o = idx & 31;
        int node = base + n;
        if (node < NN) {
            int c = g_cnt[node]; if (c < 1) c = 1;
            sm[n][o] = fmaxf(g_acc[node * DIM + o] / (float)c + cbias[o], 0.f);
            sh[n][o] = g_x[node * DIM + o];
            g_acc[node * DIM + o] = 0.f;
        }
    }
    __syncthreads();
    int warp = tid >> 5, o = tid & 31;
    int n0 = warp * 8;
    float gir[8], giz[8], gin[8], ghr[8], ghz[8], ghn[8];
    float b0 = bih[o], b1 = bih[DIM + o], b2 = bih[2 * DIM + o];
    float c0 = bhh[o], c1 = bhh[DIM + o], c2 = bhh[2 * DIM + o];
#pragma unroll
    for (int n = 0; n < 8; n++) {
        gir[n] = b0; giz[n] = b1; gin[n] = b2;
        ghr[n] = c0; ghz[n] = c1; ghn[n] = c2;
    }
#pragma unroll 4
    for (int i = 0; i < DIM; i++) {
        float wr = g_wihT[i * 96 + o], wz = g_wihT[i * 96 + DIM + o], wn_ = g_wihT[i * 96 + 2 * DIM + o];
        float vr = g_whhT[i * 96 + o], vz = g_whhT[i * 96 + DIM + o], vn = g_whhT[i * 96 + 2 * DIM + o];
#pragma unroll
        for (int n = 0; n < 8; n++) {
            float mi = sm[n0 + n][i], hi = sh[n0 + n][i];
            gir[n] = fmaf(mi, wr, gir[n]);
            giz[n] = fmaf(mi, wz, giz[n]);
            gin[n] = fmaf(mi, wn_, gin[n]);
            ghr[n] = fmaf(hi, vr, ghr[n]);
            ghz[n] = fmaf(hi, vz, ghz[n]);
            ghn[n] = fmaf(hi, vn, ghn[n]);
        }
    }
#pragma unroll
    for (int n = 0; n < 8; n++) {
        int node = base + n0 + n;
        if (node < NN) {
            float r = 1.f / (1.f + expf(-(gir[n] + ghr[n])));
            float z = 1.f / (1.f + expf(-(giz[n] + ghz[n])));
            float nv = tanhf(gin[n] + r * ghn[n]);
            g_x[node * DIM + o] = (1.f - z) * nv + z * sh[n0 + n][o];
        }
    }
}

// ---------------- fused Set2Set: one block per graph, all 3 steps + writeout ----------------
// out layout: [pooled (2000 x 64), out (100000 x 32)]
__global__ void __launch_bounds__(128) s2s_kernel(const int* __restrict__ gidx,
                                                  const float* __restrict__ bih,
                                                  const float* __restrict__ bhh,
                                                  float* __restrict__ out) {
    int g = blockIdx.x;
    int tid = threadIdx.x, lane = tid & 31, w = tid >> 5;
    __shared__ float sq[64];        // q_star
    __shared__ float sh[DIM], sc[DIM];
    __shared__ float sgate[128];
    __shared__ float red[4], sr[4][DIM], sd[4];
    __shared__ int   sse[2];

    // per-graph node range via binary search in sorted gidx
    if (tid < 2) {
        int target = g + tid;
        int lo = 0, hi = NN;
        while (lo < hi) { int mid = (lo + hi) >> 1; if (gidx[mid] < target) lo = mid + 1; else hi = mid; }
        sse[tid] = lo;
    }
    if (tid < 64) sq[tid] = 0.f;
    if (tid < DIM) { sh[tid] = 0.f; sc[tid] = 0.f; }
    __syncthreads();
    int s = sse[0], e = sse[1];

    float bsum = bih[tid] + bhh[tid];

    for (int step = 0; step < 3; step++) {
        // ---- LSTM cell: each of the 128 threads computes one gate element ----
        float gv = bsum;
        for (int i = 0; i < 64; i++) gv = fmaf(sq[i], g_lwihT[i * 128 + tid], gv);
        for (int i = 0; i < DIM; i++) gv = fmaf(sh[i], g_lwhhT[i * 128 + tid], gv);
        sgate[tid] = gv;
        __syncthreads();
        if (tid < DIM) {
            float si = 1.f / (1.f + expf(-sgate[tid]));
            float sf = 1.f / (1.f + expf(-sgate[32 + tid]));
            float gg = tanhf(sgate[64 + tid]);
            float so = 1.f / (1.f + expf(-sgate[96 + tid]));
            float cc = sf * sc[tid] + si * gg;
            sc[tid] = cc;
            sh[tid] = so * tanhf(cc);
        }
        __syncthreads();

        // ---- attention: q = sh ----
        float qv = sh[lane];
        float mx = -INFINITY;
        for (int n = s + w; n < e; n += 4) {
            float v = g_x[n * DIM + lane] * qv;
#pragma unroll
            for (int off = 16; off; off >>= 1) v += __shfl_xor_sync(0xffffffffu, v, off);
            mx = fmaxf(mx, v);
        }
        if (lane == 0) red[w] = mx;
        __syncthreads();
        mx = fmaxf(fmaxf(red[0], red[1]), fmaxf(red[2], red[3]));
        float denom = 0.f, racc = 0.f;
        for (int n = s + w; n < e; n += 4) {
            float xo = g_x[n * DIM + lane];
            float v = xo * qv;
#pragma unroll
            for (int off = 16; off; off >>= 1) v += __shfl_xor_sync(0xffffffffu, v, off);
            float ex = __expf(v - mx);
            denom += ex;
            racc = fmaf(ex, xo, racc);
        }
        sr[w][lane] = racc;
        if (lane == 0) sd[w] = denom;
        __syncthreads();
        if (w == 0) {
            float r = sr[0][lane] + sr[1][lane] + sr[2][lane] + sr[3][lane];
            float d = sd[0] + sd[1] + sd[2] + sd[3];
            r = (d > 0.f) ? r / d : 0.f;
            sq[lane] = sh[lane];
            sq[32 + lane] = r;
        }
        __syncthreads();
    }

    // ---- writeout: pooled row + this graph's node states ----
    if (tid < 64) out[g * 64 + tid] = sq[tid];
    int cnt = (e - s) * DIM;
    const float* xs = g_x + s * DIM;
    float* od = out + NB * 64 + s * DIM;
    for (int i = tid; i < cnt; i += 128) od[i] = xs[i];
}

// ---------------- launch ----------------
extern "C" void kernel_launch(void* const* d_in, const int* in_sizes, int n_in,
                              void* d_out, int out_size) {
    const float* nf        = (const float*)d_in[0];
    const float* ef        = (const float*)d_in[1];
    const float* lin0_w    = (const float*)d_in[2];
    const float* lin0_b    = (const float*)d_in[3];
    const float* nn_w1     = (const float*)d_in[4];
    const float* nn_b1     = (const float*)d_in[5];
    const float* nn_w2     = (const float*)d_in[6];
    const float* nn_b2     = (const float*)d_in[7];
    const float* conv_bias = (const float*)d_in[8];
    const float* gru_wih   = (const float*)d_in[9];
    const float* gru_whh   = (const float*)d_in[10];
    const float* gru_bih   = (const float*)d_in[11];
    const float* gru_bhh   = (const float*)d_in[12];
    const float* lstm_wih  = (const float*)d_in[13];
    const float* lstm_whh  = (const float*)d_in[14];
    const float* lstm_bih  = (const float*)d_in[15];
    const float* lstm_bhh  = (const float*)d_in[16];
    const int*   ei        = (const int*)d_in[17];
    const int*   gidx      = (const int*)d_in[18];

    static int smem_set = 0;
    if (!smem_set) {
        cudaFuncSetAttribute(gemm_fused_kernel, cudaFuncAttributeMaxDynamicSharedMemorySize,
                             SMEM_GEMM_TOTAL);
        smem_set = 1;
    }

    prep_kernel<<<512, 256>>>(lin0_w, nn_w1, gru_wih, gru_whh, lstm_wih, lstm_whh, nn_w2, nn_b2);
    lin0_kernel<<<(NN + 63) / 64, 256>>>(nf, lin0_b);  // also zeroes g_cnt / g_acc
    deg_kernel<<<(NE + 255) / 256, 256>>>(ei);
    gemm_fused_kernel<<<MPAD / 128, 256, SMEM_GEMM_TOTAL>>>(ef, nn_b1);

    for (int t = 0; t < 3; t++) {
        conv_kernel<<<NE / 8, 256>>>(ei);
        gru_kernel<<<(NN + 63) / 64, 256>>>(conv_bias, gru_bih, gru_bhh);
    }

    s2s_kernel<<<NB, 128>>>(gidx, lstm_bih, lstm_bhh, (float*)d_out);
}

// round 14
// speedup vs baseline: 1.2291x; 1.1159x over previous
#include <cuda_runtime.h>
#include <cuda_fp16.h>
#include <math.h>
#include <stdint.h>

#define NN   100000
#define NE   250000
#define NB   2000
#define FIN  75
#define DIM  32
#define HID  128
#define NOUT 1024           // DIM*DIM
#define MPAD 250112         // 1954 * 128

// ---------------- scratch (static __device__, no allocation) ----------------
__device__ __align__(16) __half g_ewb[(size_t)MPAD * NOUT];  // edge weights fp16, [o][i] per edge
__device__ __align__(16) __half g_w2b[NOUT * HID];           // W2 fp16, column-permuted (c' = o*32+i)
__device__ __align__(16) __half g_gruB[128 * 64];            // GRU combined weights [128 x 64] fp16
__device__ float g_b2p[NOUT];                                // b2 permuted
__device__ float g_x[NN * DIM];                 // node state
__device__ float g_acc[NN * DIM];               // conv scatter accumulator
__device__ int   g_cnt[NN];                     // in-degree
// transposed weights
__device__ float g_w0T[FIN * DIM];
__device__ float g_w1T[11 * HID];
__device__ float g_lwihT[64 * 128];
__device__ float g_lwhhT[DIM * 128];

__device__ __forceinline__ uint32_t smem_u32(const void* p) {
    uint32_t a;
    asm("{ .reg .u64 t; cvta.to.shared.u64 t, %1; cvt.u32.u64 %0, t; }" : "=r"(a) : "l"(p));
    return a;
}
__device__ __forceinline__ void mma_fp16(float* c, const uint32_t* a, uint32_t b0, uint32_t b1) {
    asm volatile(
        "mma.sync.aligned.m16n8k16.row.col.f32.f16.f16.f32 "
        "{%0,%1,%2,%3}, {%4,%5,%6,%7}, {%8,%9}, {%0,%1,%2,%3};"
        : "+f"(c[0]), "+f"(c[1]), "+f"(c[2]), "+f"(c[3])
        : "r"(a[0]), "r"(a[1]), "r"(a[2]), "r"(a[3]), "r"(b0), "r"(b1));
}

// ---------------- prep: transposes + fp16 W2 (col-permuted) + GRU combined B ----------------
__global__ void prep_kernel(const float* __restrict__ w0, const float* __restrict__ w1,
                            const float* __restrict__ gwih, const float* __restrict__ gwhh,
                            const float* __restrict__ lwih, const float* __restrict__ lwhh,
                            const float* __restrict__ w2, const float* __restrict__ b2) {
    int t = blockIdx.x * 256 + threadIdx.x;
    if (t < FIN * DIM) { int i = t / DIM, o = t % DIM; g_w0T[t] = w0[o * FIN + i]; }
    if (t < 11 * HID)  { int i = t / HID, j = t % HID; g_w1T[t] = w1[j * 11 + i]; }
    if (t < 64 * 128)  { int i = t / 128, r = t % 128; g_lwihT[t] = lwih[r * 64 + i]; }
    if (t < DIM * 128) { int i = t / 128, r = t % 128; g_lwhhT[t] = lwhh[r * DIM + i]; }
    if (t < NOUT) { int corig = (t & 31) * 32 + (t >> 5); g_b2p[t] = b2[corig]; }
    if (t < 128 * 64) {
        // GRU B row n' in [0,128): cols k in [0,64). k<32 -> wih part, else whh part.
        int np = t >> 6, k = t & 63;
        float v = 0.f;
        int o = np & 31, blk = np >> 5;       // blk: 0=r-sum 1=z-sum 2=gi_n 3=gh_n
        if (blk == 0) v = (k < 32) ? gwih[o * DIM + k]          : gwhh[o * DIM + (k - 32)];
        else if (blk == 1) v = (k < 32) ? gwih[(32 + o) * DIM + k]   : gwhh[(32 + o) * DIM + (k - 32)];
        else if (blk == 2) v = (k < 32) ? gwih[(64 + o) * DIM + k]   : 0.f;
        else               v = (k < 32) ? 0.f                        : gwhh[(64 + o) * DIM + (k - 32)];
        g_gruB[t] = __float2half(v);
    }
    if (t < NOUT * HID) {
        int cp = t / HID, k = t % HID;
        int corig = (cp & 31) * 32 + (cp >> 5);
        g_w2b[t] = __float2half(w2[corig * HID + k]);
    }
}

__global__ void deg_kernel(const int* __restrict__ ei) {
    int e = blockIdx.x * 256 + threadIdx.x;
    if (e < NE) atomicAdd(&g_cnt[ei[NE + e]], 1);
}

// ---------------- lin0: 64 nodes/block, 8 nodes/warp; also zeroes g_cnt / g_acc ----------------
__global__ void __launch_bounds__(256) lin0_kernel(const float* __restrict__ nf,
                                                   const float* __restrict__ b) {
    __shared__ float sf[64][FIN + 1];
    int tid = threadIdx.x;
    int base = blockIdx.x * 64;
    for (int idx = tid; idx < 64 * FIN; idx += 256) {
        int n = idx / FIN, i = idx % FIN;
        int node = base + n;
        sf[n][i] = (node < NN) ? nf[(size_t)node * FIN + i] : 0.f;
    }
    __syncthreads();
    int warp = tid >> 5, o = tid & 31;
    int n0 = warp * 8;
    float acc[8];
    float bo = b[o];
#pragma unroll
    for (int n = 0; n < 8; n++) acc[n] = bo;
    for (int i = 0; i < FIN; i++) {
        float w = g_w0T[i * DIM + o];
#pragma unroll
        for (int n = 0; n < 8; n++) acc[n] = fmaf(sf[n0 + n][i], w, acc[n]);
    }
#pragma unroll
    for (int n = 0; n < 8; n++) {
        int node = base + n0 + n;
        if (node < NN) {
            g_x[node * DIM + o] = fmaxf(acc[n], 0.f);
            g_acc[node * DIM + o] = 0.f;
            if (o == 0) g_cnt[node] = 0;
        }
    }
}

// ---- fused GEMM: per CTA of 128 edges; hw built in-smem, loop over 8 N-slabs ----
#define SM_A     0
#define SM_B     32768
#define SM_CSTG  65536
#define SM_SEF   65536
#define SM_W1T   (65536 + 6144)
#define SM_B1    (65536 + 6144 + 5632)
#define SM_BIAS  100352
#define SMEM_GEMM_TOTAL 104448
#define CSTRIDE 272

__global__ void __launch_bounds__(256) gemm_fused_kernel(const float* __restrict__ ef,
                                                         const float* __restrict__ b1) {
    extern __shared__ __align__(16) char smem[];
    uint32_t sbase = smem_u32(smem);
    float* sef   = (float*)(smem + SM_SEF);
    float* sw1t  = (float*)(smem + SM_W1T);
    float* sb1   = (float*)(smem + SM_B1);
    float* sbias = (float*)(smem + SM_BIAS);
    int tid = threadIdx.x, lane = tid & 31, wid = tid >> 5;
    int e0 = blockIdx.x * 128;

    for (int idx = tid; idx < 128 * 11; idx += 256) {
        int r = idx / 11, i = idx % 11;
        int e = e0 + r;
        sef[r * 12 + i] = (e < NE) ? ef[(size_t)e * 11 + i] : 0.f;
    }
    for (int idx = tid; idx < 11 * HID; idx += 256) sw1t[idx] = g_w1T[idx];
    if (tid < 128) sb1[tid] = b1[tid];
#pragma unroll
    for (int l = 0; l < 4; l++) sbias[tid + l * 256] = g_b2p[tid + l * 256];
    __syncthreads();

#pragma unroll
    for (int ci = 0; ci < 8; ci++) {
        int cidx = tid + ci * 256;
        int row = cidx >> 4, c = cidx & 15;
        int k0 = c * 8;
        float v[8];
#pragma unroll
        for (int j = 0; j < 8; j++) v[j] = sb1[k0 + j];
#pragma unroll
        for (int i = 0; i < 11; i++) {
            float e_ = sef[row * 12 + i];
#pragma unroll
            for (int j = 0; j < 8; j++) v[j] = fmaf(e_, sw1t[i * HID + k0 + j], v[j]);
        }
        uint32_t p[4];
#pragma unroll
        for (int j = 0; j < 4; j++) {
            __half2 h = __floats2half2_rn(fmaxf(v[2 * j], 0.f), fmaxf(v[2 * j + 1], 0.f));
            p[j] = *(uint32_t*)&h;
        }
        int cs = (c & 8) | ((c ^ row) & 7);
        *(uint4*)(smem + SM_A + row * 256 + cs * 16) = make_uint4(p[0], p[1], p[2], p[3]);
    }
    __syncthreads();

    int wm = (wid & 3) * 32;
    int wn = (wid >> 2) * 64;

    for (int nb = 0; nb < 8; nb++) {
        const uint4* gB = (const uint4*)(g_w2b + (size_t)(nb * 128) * HID);
#pragma unroll
        for (int it = 0; it < 8; it++) {
            int idx = tid + it * 256;
            int row = idx >> 4, c = idx & 15;
            uint4 v = gB[idx];
            int cs = (c & 8) | ((c ^ row) & 7);
            *(uint4*)(smem + SM_B + row * 256 + cs * 16) = v;
        }
        __syncthreads();

        float acc[2][8][4];
#pragma unroll
        for (int mb = 0; mb < 2; mb++)
#pragma unroll
            for (int nbb = 0; nbb < 8; nbb++)
#pragma unroll
                for (int q = 0; q < 4; q++) acc[mb][nbb][q] = 0.f;

#pragma unroll
        for (int ks = 0; ks < 8; ks++) {
            int ck0 = ks * 2;
            uint32_t a[2][4], b[4][4];
#pragma unroll
            for (int mb = 0; mb < 2; mb++) {
                int row = wm + mb * 16 + (lane & 7) + ((lane >> 3) & 1) * 8;
                int ck = ck0 + (lane >> 4);
                int cs = (ck & 8) | ((ck ^ row) & 7);
                uint32_t addr = sbase + SM_A + row * 256 + cs * 16;
                asm volatile("ldmatrix.sync.aligned.m8n8.x4.shared.b16 {%0,%1,%2,%3}, [%4];"
                             : "=r"(a[mb][0]), "=r"(a[mb][1]), "=r"(a[mb][2]), "=r"(a[mb][3])
                             : "r"(addr));
            }
#pragma unroll
            for (int nb4 = 0; nb4 < 4; nb4++) {
                int t = lane >> 3, r = lane & 7;
                int n = wn + nb4 * 16 + r + (t >> 1) * 8;
                int ck = ck0 + (t & 1);
                int cs = (ck & 8) | ((ck ^ n) & 7);
                uint32_t addr = sbase + SM_B + n * 256 + cs * 16;
                asm volatile("ldmatrix.sync.aligned.m8n8.x4.shared.b16 {%0,%1,%2,%3}, [%4];"
                             : "=r"(b[nb4][0]), "=r"(b[nb4][1]), "=r"(b[nb4][2]), "=r"(b[nb4][3])
                             : "r"(addr));
            }
#pragma unroll
            for (int mb = 0; mb < 2; mb++)
#pragma unroll
                for (int nbb = 0; nbb < 8; nbb++)
                    mma_fp16(acc[mb][nbb], a[mb], b[nbb >> 1][(nbb & 1) * 2], b[nbb >> 1][(nbb & 1) * 2 + 1]);
        }
        __syncthreads();

        int g = lane >> 2, tg = lane & 3;
#pragma unroll
        for (int mb = 0; mb < 2; mb++)
#pragma unroll
            for (int nbb = 0; nbb < 8; nbb++) {
                int rowl = wm + mb * 16 + g;
                int nl = wn + nbb * 8 + tg * 2;
                float bb0 = sbias[nb * 128 + nl], bb1 = sbias[nb * 128 + nl + 1];
                float* c = acc[mb][nbb];
                __half2 p0 = __floats2half2_rn(c[0] + bb0, c[1] + bb1);
                __half2 p1 = __floats2half2_rn(c[2] + bb0, c[3] + bb1);
                *(uint32_t*)(smem + SM_CSTG + rowl * CSTRIDE + nl * 2) = *(uint32_t*)&p0;
                *(uint32_t*)(smem + SM_CSTG + (rowl + 8) * CSTRIDE + nl * 2) = *(uint32_t*)&p1;
            }
        __syncthreads();

        __half* dst = g_ewb + (size_t)e0 * NOUT + nb * 128;
#pragma unroll
        for (int it = 0; it < 8; it++) {
            int idx = tid + it * 256;
            int row = idx >> 4, c = idx & 15;
            uint4 v = *(const uint4*)(smem + SM_CSTG + row * CSTRIDE + c * 16);
            *(uint4*)(dst + (size_t)row * NOUT + c * 8) = v;
        }
        __syncthreads();
    }
}

// ---------------- NNConv: warp per edge, lane = output channel ----------------
__global__ void conv_kernel(const int* __restrict__ ei) {
    int e = blockIdx.x * 8 + (threadIdx.x >> 5);
    if (e >= NE) return;
    int o = threadIdx.x & 31;
    int src = ei[e];
    int dst = ei[NE + e];
    float xv = g_x[src * DIM + o];
    const uint4* w = (const uint4*)(g_ewb + (size_t)e * NOUT + o * 32);
    uint4 w0 = w[0], w1 = w[1], w2 = w[2], w3 = w[3];
    uint32_t ws[16] = {w0.x, w0.y, w0.z, w0.w, w1.x, w1.y, w1.z, w1.w,
                       w2.x, w2.y, w2.z, w2.w, w3.x, w3.y, w3.z, w3.w};
    float acc = 0.f;
#pragma unroll
    for (int i = 0; i < 16; i++) {
        float2 wp = __half22float2(*(__half2*)&ws[i]);
        float x0 = __shfl_sync(0xffffffffu, xv, 2 * i);
        float x1 = __shfl_sync(0xffffffffu, xv, 2 * i + 1);
        acc = fmaf(x0, wp.x, fmaf(x1, wp.y, acc));
    }
    atomicAdd(&g_acc[dst * DIM + o], acc);
}

// ---------------- GRU via mma: 64 nodes/block, gates = [m|h] @ W'^T ----------------
// smem: SA fp16[64x64] swizzled (8KB) | SB fp16[128x64] swizzled (16KB) |
//       SHF fp32[64][32] (8KB) | SD fp32 stride 132 (33.8KB)
#define GSA   0
#define GSB   8192
#define GSHF  24576
#define GSD   32768
#define GRU_SMEM (32768 + 64 * 132 * 4)   // 66560

__global__ void __launch_bounds__(256) gru_mma_kernel(const float* __restrict__ cbias,
                                                      const float* __restrict__ bih,
                                                      const float* __restrict__ bhh) {
    extern __shared__ __align__(16) char smem[];
    uint32_t sbase = smem_u32(smem);
    float* shf = (float*)(smem + GSHF);
    float* sD  = (float*)(smem + GSD);
    int tid = threadIdx.x, lane = tid & 31, wid = tid >> 5;
    int base = blockIdx.x * 64;

    // load B (same for all blocks): 128 rows x 128B = 1024 chunks
#pragma unroll
    for (int l = 0; l < 4; l++) {
        int idx = tid + l * 256;
        int row = idx >> 3, c = idx & 7;
        int cs = c ^ (row & 7);
        *(uint4*)(smem + GSB + row * 128 + cs * 16) = ((const uint4*)g_gruB)[idx];
    }
    // build A tile: cols 0-31 = m (relu(acc/deg + cbias)), cols 32-63 = h; fp16 swizzled
#pragma unroll
    for (int l = 0; l < 16; l++) {
        int idx = tid + l * 256;
        int n = idx >> 6, col = idx & 63;
        int node = base + n;
        float v = 0.f;
        if (node < NN) {
            if (col < 32) {
                int c = g_cnt[node]; if (c < 1) c = 1;
                v = fmaxf(g_acc[node * DIM + col] / (float)c + cbias[col], 0.f);
                g_acc[node * DIM + col] = 0.f;     // ready for next conv iteration
            } else {
                v = g_x[node * DIM + (col - 32)];
                shf[n * 32 + (col - 32)] = v;
            }
        } else if (col >= 32) shf[n * 32 + (col - 32)] = 0.f;
        int c = col >> 3;
        int cs = c ^ (n & 7);
        *(__half*)(smem + GSA + n * 128 + cs * 16 + (col & 7) * 2) = __float2half(v);
    }
    __syncthreads();

    // mma: warps 4M x 2N; warp tile 16 rows x 64 cols
    int wm = (wid & 3) * 16;
    int wn = (wid >> 2) * 64;
    float acc[8][4];
#pragma unroll
    for (int nbb = 0; nbb < 8; nbb++)
#pragma unroll
        for (int q = 0; q < 4; q++) acc[nbb][q] = 0.f;

#pragma unroll
    for (int ks = 0; ks < 4; ks++) {
        int ck0 = ks * 2;
        uint32_t a[4], b[4][4];
        {
            int row = wm + (lane & 7) + ((lane >> 3) & 1) * 8;
            int ck = ck0 + (lane >> 4);
            int cs = ck ^ (row & 7);
            uint32_t addr = sbase + GSA + row * 128 + cs * 16;
            asm volatile("ldmatrix.sync.aligned.m8n8.x4.shared.b16 {%0,%1,%2,%3}, [%4];"
                         : "=r"(a[0]), "=r"(a[1]), "=r"(a[2]), "=r"(a[3]) : "r"(addr));
        }
#pragma unroll
        for (int nb4 = 0; nb4 < 4; nb4++) {
            int t = lane >> 3, r = lane & 7;
            int n = wn + nb4 * 16 + r + (t >> 1) * 8;
            int ck = ck0 + (t & 1);
            int cs = ck ^ (n & 7);
            uint32_t addr = sbase + GSB + n * 128 + cs * 16;
            asm volatile("ldmatrix.sync.aligned.m8n8.x4.shared.b16 {%0,%1,%2,%3}, [%4];"
                         : "=r"(b[nb4][0]), "=r"(b[nb4][1]), "=r"(b[nb4][2]), "=r"(b[nb4][3])
                         : "r"(addr));
        }
#pragma unroll
        for (int nbb = 0; nbb < 8; nbb++)
            mma_fp16(acc[nbb], a, b[nbb >> 1][(nbb & 1) * 2], b[nbb >> 1][(nbb & 1) * 2 + 1]);
    }

    // stage D (raw fp32) to smem, stride 132 floats
    int g = lane >> 2, tg = lane & 3;
#pragma unroll
    for (int nbb = 0; nbb < 8; nbb++) {
        int rowl = wm + g;
        int nl = wn + nbb * 8 + tg * 2;
        float* c = acc[nbb];
        *(float2*)&sD[rowl * 132 + nl] = make_float2(c[0], c[1]);
        *(float2*)&sD[(rowl + 8) * 132 + nl] = make_float2(c[2], c[3]);
    }
    __syncthreads();

    // epilogue: gates -> new x
    float br  = bih[lane] + bhh[lane];
    float bz  = bih[32 + lane] + bhh[32 + lane];
    float bin = bih[64 + lane];
    float bhn = bhh[64 + lane];
#pragma unroll
    for (int l = 0; l < 8; l++) {
        int idx = tid + l * 256;
        int n = idx >> 5, o = idx & 31;   // o == lane
        int node = base + n;
        if (node < NN) {
            const float* d = &sD[n * 132];
            float r = 1.f / (1.f + expf(-(d[o] + br)));
            float z = 1.f / (1.f + expf(-(d[32 + o] + bz)));
            float nv = tanhf(d[64 + o] + bin + r * (d[96 + o] + bhn));
            float h = shf[n * 32 + o];
            g_x[node * DIM + o] = (1.f - z) * nv + z * h;
        }
    }
}

// ---------------- fused Set2Set: one block per graph, all 3 steps + writeout ----------------
__global__ void __launch_bounds__(128) s2s_kernel(const int* __restrict__ gidx,
                                                  const float* __restrict__ bih,
                                                  const float* __restrict__ bhh,
                                                  float* __restrict__ out) {
    int g = blockIdx.x;
    int tid = threadIdx.x, lane = tid & 31, w = tid >> 5;
    __shared__ float sq[64];
    __shared__ float sh[DIM], sc[DIM];
    __shared__ float sgate[128];
    __shared__ float red[4], sr[4][DIM], sd[4];
    __shared__ int   sse[2];

    if (tid < 2) {
        int target = g + tid;
        int lo = 0, hi = NN;
        while (lo < hi) { int mid = (lo + hi) >> 1; if (gidx[mid] < target) lo = mid + 1; else hi = mid; }
        sse[tid] = lo;
    }
    if (tid < 64) sq[tid] = 0.f;
    if (tid < DIM) { sh[tid] = 0.f; sc[tid] = 0.f; }
    __syncthreads();
    int s = sse[0], e = sse[1];

    float bsum = bih[tid] + bhh[tid];

    for (int step = 0; step < 3; step++) {
        float gv = bsum;
        for (int i = 0; i < 64; i++) gv = fmaf(sq[i], g_lwihT[i * 128 + tid], gv);
        for (int i = 0; i < DIM; i++) gv = fmaf(sh[i], g_lwhhT[i * 128 + tid], gv);
        sgate[tid] = gv;
        __syncthreads();
        if (tid < DIM) {
            float si = 1.f / (1.f + expf(-sgate[tid]));
            float sf = 1.f / (1.f + expf(-sgate[32 + tid]));
            float gg = tanhf(sgate[64 + tid]);
            float so = 1.f / (1.f + expf(-sgate[96 + tid]));
            float cc = sf * sc[tid] + si * gg;
            sc[tid] = cc;
            sh[tid] = so * tanhf(cc);
        }
        __syncthreads();

        float qv = sh[lane];
        float mx = -INFINITY;
        for (int n = s + w; n < e; n += 4) {
            float v = g_x[n * DIM + lane] * qv;
#pragma unroll
            for (int off = 16; off; off >>= 1) v += __shfl_xor_sync(0xffffffffu, v, off);
            mx = fmaxf(mx, v);
        }
        if (lane == 0) red[w] = mx;
        __syncthreads();
        mx = fmaxf(fmaxf(red[0], red[1]), fmaxf(red[2], red[3]));
        float denom = 0.f, racc = 0.f;
        for (int n = s + w; n < e; n += 4) {
            float xo = g_x[n * DIM + lane];
            float v = xo * qv;
#pragma unroll
            for (int off = 16; off; off >>= 1) v += __shfl_xor_sync(0xffffffffu, v, off);
            float ex = __expf(v - mx);
            denom += ex;
            racc = fmaf(ex, xo, racc);
        }
        sr[w][lane] = racc;
        if (lane == 0) sd[w] = denom;
        __syncthreads();
        if (w == 0) {
            float r = sr[0][lane] + sr[1][lane] + sr[2][lane] + sr[3][lane];
            float d = sd[0] + sd[1] + sd[2] + sd[3];
            r = (d > 0.f) ? r / d : 0.f;
            sq[lane] = sh[lane];
            sq[32 + lane] = r;
        }
        __syncthreads();
    }

    if (tid < 64) out[g * 64 + tid] = sq[tid];
    int cnt = (e - s) * DIM;
    const float* xs = g_x + s * DIM;
    float* od = out + NB * 64 + s * DIM;
    for (int i = tid; i < cnt; i += 128) od[i] = xs[i];
}

// ---------------- launch ----------------
extern "C" void kernel_launch(void* const* d_in, const int* in_sizes, int n_in,
                              void* d_out, int out_size) {
    const float* nf        = (const float*)d_in[0];
    const float* ef        = (const float*)d_in[1];
    const float* lin0_w    = (const float*)d_in[2];
    const float* lin0_b    = (const float*)d_in[3];
    const float* nn_w1     = (const float*)d_in[4];
    const float* nn_b1     = (const float*)d_in[5];
    const float* nn_w2     = (const float*)d_in[6];
    const float* nn_b2     = (const float*)d_in[7];
    const float* conv_bias = (const float*)d_in[8];
    const float* gru_wih   = (const float*)d_in[9];
    const float* gru_whh   = (const float*)d_in[10];
    const float* gru_bih   = (const float*)d_in[11];
    const float* gru_bhh   = (const float*)d_in[12];
    const float* lstm_wih  = (const float*)d_in[13];
    const float* lstm_whh  = (const float*)d_in[14];
    const float* lstm_bih  = (const float*)d_in[15];
    const float* lstm_bhh  = (const float*)d_in[16];
    const int*   ei        = (const int*)d_in[17];
    const int*   gidx      = (const int*)d_in[18];

    static int smem_set = 0;
    if (!smem_set) {
        cudaFuncSetAttribute(gemm_fused_kernel, cudaFuncAttributeMaxDynamicSharedMemorySize,
                             SMEM_GEMM_TOTAL);
        cudaFuncSetAttribute(gru_mma_kernel, cudaFuncAttributeMaxDynamicSharedMemorySize,
                             GRU_SMEM);
        smem_set = 1;
    }

    prep_kernel<<<512, 256>>>(lin0_w, nn_w1, gru_wih, gru_whh, lstm_wih, lstm_whh, nn_w2, nn_b2);
    lin0_kernel<<<(NN + 63) / 64, 256>>>(nf, lin0_b);  // also zeroes g_cnt / g_acc
    deg_kernel<<<(NE + 255) / 256, 256>>>(ei);
    gemm_fused_kernel<<<MPAD / 128, 256, SMEM_GEMM_TOTAL>>>(ef, nn_b1);

    for (int t = 0; t < 3; t++) {
        conv_kernel<<<NE / 8, 256>>>(ei);
        gru_mma_kernel<<<(NN + 63) / 64, 256, GRU_SMEM>>>(conv_bias, gru_bih, gru_bhh);
    }

    s2s_kernel<<<NB, 128>>>(gidx, lstm_bih, lstm_bhh, (float*)d_out);
}

// round 15
// speedup vs baseline: 1.3372x; 1.0880x over previous
#include <cuda_runtime.h>
#include <cuda_fp16.h>
#include <math.h>
#include <stdint.h>

#define NN   100000
#define NE   250000
#define NB   2000
#define FIN  75
#define DIM  32
#define HID  128
#define NOUT 1024           // DIM*DIM
#define MPAD 250112         // 1954 * 128

// ---------------- scratch (static __device__, no allocation) ----------------
__device__ __align__(16) __half g_ewb[(size_t)MPAD * NOUT];  // edge weights fp16, [o][i] per edge
__device__ __align__(16) __half g_w2b[NOUT * HID];           // W2 fp16, column-permuted (c' = o*32+i)
__device__ __align__(16) __half g_gruB[128 * 64];            // GRU combined weights [128 x 64] fp16
__device__ float g_b2p[NOUT];                                // b2 permuted
__device__ float g_x[NN * DIM];                 // node state
__device__ float g_acc[NN * DIM];               // conv scatter accumulator
__device__ int   g_cnt[NN];                     // in-degree
// transposed weights
__device__ float g_w0T[FIN * DIM];
__device__ float g_w1T[11 * HID];
__device__ float g_lwihT[64 * 128];
__device__ float g_lwhhT[DIM * 128];

__device__ __forceinline__ uint32_t smem_u32(const void* p) {
    uint32_t a;
    asm("{ .reg .u64 t; cvta.to.shared.u64 t, %1; cvt.u32.u64 %0, t; }" : "=r"(a) : "l"(p));
    return a;
}
__device__ __forceinline__ void mma_fp16(float* c, const uint32_t* a, uint32_t b0, uint32_t b1) {
    asm volatile(
        "mma.sync.aligned.m16n8k16.row.col.f32.f16.f16.f32 "
        "{%0,%1,%2,%3}, {%4,%5,%6,%7}, {%8,%9}, {%0,%1,%2,%3};"
        : "+f"(c[0]), "+f"(c[1]), "+f"(c[2]), "+f"(c[3])
        : "r"(a[0]), "r"(a[1]), "r"(a[2]), "r"(a[3]), "r"(b0), "r"(b1));
}

// ---------------- prep: transposes + fp16 W2 (col-permuted) + GRU combined B ----------------
__global__ void prep_kernel(const float* __restrict__ w0, const float* __restrict__ w1,
                            const float* __restrict__ gwih, const float* __restrict__ gwhh,
                            const float* __restrict__ lwih, const float* __restrict__ lwhh,
                            const float* __restrict__ w2, const float* __restrict__ b2) {
    int t = blockIdx.x * 256 + threadIdx.x;
    if (t < FIN * DIM) { int i = t / DIM, o = t % DIM; g_w0T[t] = w0[o * FIN + i]; }
    if (t < 11 * HID)  { int i = t / HID, j = t % HID; g_w1T[t] = w1[j * 11 + i]; }
    if (t < 64 * 128)  { int i = t / 128, r = t % 128; g_lwihT[t] = lwih[r * 64 + i]; }
    if (t < DIM * 128) { int i = t / 128, r = t % 128; g_lwhhT[t] = lwhh[r * DIM + i]; }
    if (t < NOUT) { int corig = (t & 31) * 32 + (t >> 5); g_b2p[t] = b2[corig]; }
    if (t < 128 * 64) {
        int np = t >> 6, k = t & 63;
        float v = 0.f;
        int o = np & 31, blk = np >> 5;       // blk: 0=r-sum 1=z-sum 2=gi_n 3=gh_n
        if (blk == 0) v = (k < 32) ? gwih[o * DIM + k]          : gwhh[o * DIM + (k - 32)];
        else if (blk == 1) v = (k < 32) ? gwih[(32 + o) * DIM + k]   : gwhh[(32 + o) * DIM + (k - 32)];
        else if (blk == 2) v = (k < 32) ? gwih[(64 + o) * DIM + k]   : 0.f;
        else               v = (k < 32) ? 0.f                        : gwhh[(64 + o) * DIM + (k - 32)];
        g_gruB[t] = __float2half(v);
    }
    if (t < NOUT * HID) {
        int cp = t / HID, k = t % HID;
        int corig = (cp & 31) * 32 + (cp >> 5);
        g_w2b[t] = __float2half(w2[corig * HID + k]);
    }
}

__global__ void deg_kernel(const int* __restrict__ ei) {
    int e = blockIdx.x * 256 + threadIdx.x;
    if (e < NE) atomicAdd(&g_cnt[ei[NE + e]], 1);
}

// ---------------- lin0: 64 nodes/block, 8 nodes/warp; also zeroes g_cnt / g_acc ----------------
__global__ void __launch_bounds__(256) lin0_kernel(const float* __restrict__ nf,
                                                   const float* __restrict__ b) {
    __shared__ float sf[64][FIN + 1];
    int tid = threadIdx.x;
    int base = blockIdx.x * 64;
    for (int idx = tid; idx < 64 * FIN; idx += 256) {
        int n = idx / FIN, i = idx % FIN;
        int node = base + n;
        sf[n][i] = (node < NN) ? nf[(size_t)node * FIN + i] : 0.f;
    }
    __syncthreads();
    int warp = tid >> 5, o = tid & 31;
    int n0 = warp * 8;
    float acc[8];
    float bo = b[o];
#pragma unroll
    for (int n = 0; n < 8; n++) acc[n] = bo;
    for (int i = 0; i < FIN; i++) {
        float w = g_w0T[i * DIM + o];
#pragma unroll
        for (int n = 0; n < 8; n++) acc[n] = fmaf(sf[n0 + n][i], w, acc[n]);
    }
#pragma unroll
    for (int n = 0; n < 8; n++) {
        int node = base + n0 + n;
        if (node < NN) {
            g_x[node * DIM + o] = fmaxf(acc[n], 0.f);
            g_acc[node * DIM + o] = 0.f;
            if (o == 0) g_cnt[node] = 0;
        }
    }
}

// ---- fused GEMM: per CTA of 128 edges; hw built in-smem, loop over 8 N-slabs ----
#define SM_A     0
#define SM_B     32768
#define SM_CSTG  65536
#define SM_SEF   65536
#define SM_W1T   (65536 + 6144)
#define SM_B1    (65536 + 6144 + 5632)
#define SM_BIAS  100352
#define SMEM_GEMM_TOTAL 104448
#define CSTRIDE 272

__global__ void __launch_bounds__(256) gemm_fused_kernel(const float* __restrict__ ef,
                                                         const float* __restrict__ b1) {
    extern __shared__ __align__(16) char smem[];
    uint32_t sbase = smem_u32(smem);
    float* sef   = (float*)(smem + SM_SEF);
    float* sw1t  = (float*)(smem + SM_W1T);
    float* sb1   = (float*)(smem + SM_B1);
    float* sbias = (float*)(smem + SM_BIAS);
    int tid = threadIdx.x, lane = tid & 31, wid = tid >> 5;
    int e0 = blockIdx.x * 128;

    for (int idx = tid; idx < 128 * 11; idx += 256) {
        int r = idx / 11, i = idx % 11;
        int e = e0 + r;
        sef[r * 12 + i] = (e < NE) ? ef[(size_t)e * 11 + i] : 0.f;
    }
    for (int idx = tid; idx < 11 * HID; idx += 256) sw1t[idx] = g_w1T[idx];
    if (tid < 128) sb1[tid] = b1[tid];
#pragma unroll
    for (int l = 0; l < 4; l++) sbias[tid + l * 256] = g_b2p[tid + l * 256];
    __syncthreads();

#pragma unroll
    for (int ci = 0; ci < 8; ci++) {
        int cidx = tid + ci * 256;
        int row = cidx >> 4, c = cidx & 15;
        int k0 = c * 8;
        float v[8];
#pragma unroll
        for (int j = 0; j < 8; j++) v[j] = sb1[k0 + j];
#pragma unroll
        for (int i = 0; i < 11; i++) {
            float e_ = sef[row * 12 + i];
#pragma unroll
            for (int j = 0; j < 8; j++) v[j] = fmaf(e_, sw1t[i * HID + k0 + j], v[j]);
        }
        uint32_t p[4];
#pragma unroll
        for (int j = 0; j < 4; j++) {
            __half2 h = __floats2half2_rn(fmaxf(v[2 * j], 0.f), fmaxf(v[2 * j + 1], 0.f));
            p[j] = *(uint32_t*)&h;
        }
        int cs = (c & 8) | ((c ^ row) & 7);
        *(uint4*)(smem + SM_A + row * 256 + cs * 16) = make_uint4(p[0], p[1], p[2], p[3]);
    }
    __syncthreads();

    int wm = (wid & 3) * 32;
    int wn = (wid >> 2) * 64;

    for (int nb = 0; nb < 8; nb++) {
        const uint4* gB = (const uint4*)(g_w2b + (size_t)(nb * 128) * HID);
#pragma unroll
        for (int it = 0; it < 8; it++) {
            int idx = tid + it * 256;
            int row = idx >> 4, c = idx & 15;
            uint4 v = gB[idx];
            int cs = (c & 8) | ((c ^ row) & 7);
            *(uint4*)(smem + SM_B + row * 256 + cs * 16) = v;
        }
        __syncthreads();

        float acc[2][8][4];
#pragma unroll
        for (int mb = 0; mb < 2; mb++)
#pragma unroll
            for (int nbb = 0; nbb < 8; nbb++)
#pragma unroll
                for (int q = 0; q < 4; q++) acc[mb][nbb][q] = 0.f;

#pragma unroll
        for (int ks = 0; ks < 8; ks++) {
            int ck0 = ks * 2;
            uint32_t a[2][4], b[4][4];
#pragma unroll
            for (int mb = 0; mb < 2; mb++) {
                int row = wm + mb * 16 + (lane & 7) + ((lane >> 3) & 1) * 8;
                int ck = ck0 + (lane >> 4);
                int cs = (ck & 8) | ((ck ^ row) & 7);
                uint32_t addr = sbase + SM_A + row * 256 + cs * 16;
                asm volatile("ldmatrix.sync.aligned.m8n8.x4.shared.b16 {%0,%1,%2,%3}, [%4];"
                             : "=r"(a[mb][0]), "=r"(a[mb][1]), "=r"(a[mb][2]), "=r"(a[mb][3])
                             : "r"(addr));
            }
#pragma unroll
            for (int nb4 = 0; nb4 < 4; nb4++) {
                int t = lane >> 3, r = lane & 7;
                int n = wn + nb4 * 16 + r + (t >> 1) * 8;
                int ck = ck0 + (t & 1);
                int cs = (ck & 8) | ((ck ^ n) & 7);
                uint32_t addr = sbase + SM_B + n * 256 + cs * 16;
                asm volatile("ldmatrix.sync.aligned.m8n8.x4.shared.b16 {%0,%1,%2,%3}, [%4];"
                             : "=r"(b[nb4][0]), "=r"(b[nb4][1]), "=r"(b[nb4][2]), "=r"(b[nb4][3])
                             : "r"(addr));
            }
#pragma unroll
            for (int mb = 0; mb < 2; mb++)
#pragma unroll
                for (int nbb = 0; nbb < 8; nbb++)
                    mma_fp16(acc[mb][nbb], a[mb], b[nbb >> 1][(nbb & 1) * 2], b[nbb >> 1][(nbb & 1) * 2 + 1]);
        }
        __syncthreads();

        int g = lane >> 2, tg = lane & 3;
#pragma unroll
        for (int mb = 0; mb < 2; mb++)
#pragma unroll
            for (int nbb = 0; nbb < 8; nbb++) {
                int rowl = wm + mb * 16 + g;
                int nl = wn + nbb * 8 + tg * 2;
                float bb0 = sbias[nb * 128 + nl], bb1 = sbias[nb * 128 + nl + 1];
                float* c = acc[mb][nbb];
                __half2 p0 = __floats2half2_rn(c[0] + bb0, c[1] + bb1);
                __half2 p1 = __floats2half2_rn(c[2] + bb0, c[3] + bb1);
                *(uint32_t*)(smem + SM_CSTG + rowl * CSTRIDE + nl * 2) = *(uint32_t*)&p0;
                *(uint32_t*)(smem + SM_CSTG + (rowl + 8) * CSTRIDE + nl * 2) = *(uint32_t*)&p1;
            }
        __syncthreads();

        __half* dst = g_ewb + (size_t)e0 * NOUT + nb * 128;
#pragma unroll
        for (int it = 0; it < 8; it++) {
            int idx = tid + it * 256;
            int row = idx >> 4, c = idx & 15;
            uint4 v = *(const uint4*)(smem + SM_CSTG + row * CSTRIDE + c * 16);
            *(uint4*)(dst + (size_t)row * NOUT + c * 8) = v;
        }
        __syncthreads();
    }
}

// ---------------- NNConv: warp per edge, lane = output channel ----------------
__global__ void conv_kernel(const int* __restrict__ ei) {
    int e = blockIdx.x * 8 + (threadIdx.x >> 5);
    if (e >= NE) return;
    int o = threadIdx.x & 31;
    int src = ei[e];
    int dst = ei[NE + e];
    float xv = g_x[src * DIM + o];
    const uint4* w = (const uint4*)(g_ewb + (size_t)e * NOUT + o * 32);
    uint4 w0 = w[0], w1 = w[1], w2 = w[2], w3 = w[3];
    uint32_t ws[16] = {w0.x, w0.y, w0.z, w0.w, w1.x, w1.y, w1.z, w1.w,
                       w2.x, w2.y, w2.z, w2.w, w3.x, w3.y, w3.z, w3.w};
    float acc = 0.f;
#pragma unroll
    for (int i = 0; i < 16; i++) {
        float2 wp = __half22float2(*(__half2*)&ws[i]);
        float x0 = __shfl_sync(0xffffffffu, xv, 2 * i);
        float x1 = __shfl_sync(0xffffffffu, xv, 2 * i + 1);
        acc = fmaf(x0, wp.x, fmaf(x1, wp.y, acc));
    }
    atomicAdd(&g_acc[dst * DIM + o], acc);
}

// ---------------- GRU via mma: 64 nodes/block, gates = [m|h] @ W'^T ----------------
#define GSA   0
#define GSB   8192
#define GSHF  24576
#define GSD   32768
#define GRU_SMEM (32768 + 64 * 132 * 4)   // 66560

__global__ void __launch_bounds__(256) gru_mma_kernel(const float* __restrict__ cbias,
                                                      const float* __restrict__ bih,
                                                      const float* __restrict__ bhh) {
    extern __shared__ __align__(16) char smem[];
    uint32_t sbase = smem_u32(smem);
    float* shf = (float*)(smem + GSHF);
    float* sD  = (float*)(smem + GSD);
    int tid = threadIdx.x, lane = tid & 31, wid = tid >> 5;
    int base = blockIdx.x * 64;

    // load B: 128 rows x 128B = 1024 chunks
#pragma unroll
    for (int l = 0; l < 4; l++) {
        int idx = tid + l * 256;
        int row = idx >> 3, c = idx & 7;
        int cs = c ^ (row & 7);
        *(uint4*)(smem + GSB + row * 128 + cs * 16) = ((const uint4*)g_gruB)[idx];
    }
    // build A tile vectorized: chunk = 8 cols; chunks 0-3 = m, 4-7 = h
#pragma unroll
    for (int l = 0; l < 2; l++) {
        int idx = tid + l * 256;           // [0, 512)
        int n = idx >> 3, c = idx & 7;
        int node = base + n;
        float v[8];
        if (node < NN) {
            if (c < 4) {
                int k0 = c * 8;
                float4 a0 = *(float4*)&g_acc[node * DIM + k0];
                float4 a1 = *(float4*)&g_acc[node * DIM + k0 + 4];
                float4 cb0 = *(const float4*)&cbias[k0];
                float4 cb1 = *(const float4*)&cbias[k0 + 4];
                int cnt = g_cnt[node]; if (cnt < 1) cnt = 1;
                float fc = (float)cnt;
                v[0] = fmaxf(a0.x / fc + cb0.x, 0.f);
                v[1] = fmaxf(a0.y / fc + cb0.y, 0.f);
                v[2] = fmaxf(a0.z / fc + cb0.z, 0.f);
                v[3] = fmaxf(a0.w / fc + cb0.w, 0.f);
                v[4] = fmaxf(a1.x / fc + cb1.x, 0.f);
                v[5] = fmaxf(a1.y / fc + cb1.y, 0.f);
                v[6] = fmaxf(a1.z / fc + cb1.z, 0.f);
                v[7] = fmaxf(a1.w / fc + cb1.w, 0.f);
                *(float4*)&g_acc[node * DIM + k0]     = make_float4(0.f, 0.f, 0.f, 0.f);
                *(float4*)&g_acc[node * DIM + k0 + 4] = make_float4(0.f, 0.f, 0.f, 0.f);
            } else {
                int k0 = (c - 4) * 8;
                float4 h0 = *(float4*)&g_x[node * DIM + k0];
                float4 h1 = *(float4*)&g_x[node * DIM + k0 + 4];
                v[0] = h0.x; v[1] = h0.y; v[2] = h0.z; v[3] = h0.w;
                v[4] = h1.x; v[5] = h1.y; v[6] = h1.z; v[7] = h1.w;
                *(float4*)&shf[n * 32 + k0]     = h0;
                *(float4*)&shf[n * 32 + k0 + 4] = h1;
            }
        } else {
#pragma unroll
            for (int j = 0; j < 8; j++) v[j] = 0.f;
            if (c >= 4) {
                int k0 = (c - 4) * 8;
                *(float4*)&shf[n * 32 + k0]     = make_float4(0.f, 0.f, 0.f, 0.f);
                *(float4*)&shf[n * 32 + k0 + 4] = make_float4(0.f, 0.f, 0.f, 0.f);
            }
        }
        uint32_t p[4];
#pragma unroll
        for (int j = 0; j < 4; j++) {
            __half2 h = __floats2half2_rn(v[2 * j], v[2 * j + 1]);
            p[j] = *(uint32_t*)&h;
        }
        int cs = c ^ (n & 7);
        *(uint4*)(smem + GSA + n * 128 + cs * 16) = make_uint4(p[0], p[1], p[2], p[3]);
    }
    __syncthreads();

    // mma: warps 4M x 2N; warp tile 16 rows x 64 cols
    int wm = (wid & 3) * 16;
    int wn = (wid >> 2) * 64;
    float acc[8][4];
#pragma unroll
    for (int nbb = 0; nbb < 8; nbb++)
#pragma unroll
        for (int q = 0; q < 4; q++) acc[nbb][q] = 0.f;

#pragma unroll
    for (int ks = 0; ks < 4; ks++) {
        int ck0 = ks * 2;
        uint32_t a[4], b[4][4];
        {
            int row = wm + (lane & 7) + ((lane >> 3) & 1) * 8;
            int ck = ck0 + (lane >> 4);
            int cs = ck ^ (row & 7);
            uint32_t addr = sbase + GSA + row * 128 + cs * 16;
            asm volatile("ldmatrix.sync.aligned.m8n8.x4.shared.b16 {%0,%1,%2,%3}, [%4];"
                         : "=r"(a[0]), "=r"(a[1]), "=r"(a[2]), "=r"(a[3]) : "r"(addr));
        }
#pragma unroll
        for (int nb4 = 0; nb4 < 4; nb4++) {
            int t = lane >> 3, r = lane & 7;
            int n = wn + nb4 * 16 + r + (t >> 1) * 8;
            int ck = ck0 + (t & 1);
            int cs = ck ^ (n & 7);
            uint32_t addr = sbase + GSB + n * 128 + cs * 16;
            asm volatile("ldmatrix.sync.aligned.m8n8.x4.shared.b16 {%0,%1,%2,%3}, [%4];"
                         : "=r"(b[nb4][0]), "=r"(b[nb4][1]), "=r"(b[nb4][2]), "=r"(b[nb4][3])
                         : "r"(addr));
        }
#pragma unroll
        for (int nbb = 0; nbb < 8; nbb++)
            mma_fp16(acc[nbb], a, b[nbb >> 1][(nbb & 1) * 2], b[nbb >> 1][(nbb & 1) * 2 + 1]);
    }

    // stage D (raw fp32) to smem, stride 132 floats
    int g = lane >> 2, tg = lane & 3;
#pragma unroll
    for (int nbb = 0; nbb < 8; nbb++) {
        int rowl = wm + g;
        int nl = wn + nbb * 8 + tg * 2;
        float* c = acc[nbb];
        *(float2*)&sD[rowl * 132 + nl] = make_float2(c[0], c[1]);
        *(float2*)&sD[(rowl + 8) * 132 + nl] = make_float2(c[2], c[3]);
    }
    __syncthreads();

    // epilogue: gates -> new x
    float br  = bih[lane] + bhh[lane];
    float bz  = bih[32 + lane] + bhh[32 + lane];
    float bin = bih[64 + lane];
    float bhn = bhh[64 + lane];
#pragma unroll
    for (int l = 0; l < 8; l++) {
        int idx = tid + l * 256;
        int n = idx >> 5, o = idx & 31;   // o == lane
        int node = base + n;
        if (node < NN) {
            const float* d = &sD[n * 132];
            float r = 1.f / (1.f + expf(-(d[o] + br)));
            float z = 1.f / (1.f + expf(-(d[32 + o] + bz)));
            float nv = tanhf(d[64 + o] + bin + r * (d[96 + o] + bhn));
            float h = shf[n * 32 + o];
            g_x[node * DIM + o] = (1.f - z) * nv + z * h;
        }
    }
}

// ---------------- fused Set2Set: one block per graph, all 3 steps + writeout ----------------
__global__ void __launch_bounds__(128) s2s_kernel(const int* __restrict__ gidx,
                                                  const float* __restrict__ bih,
                                                  const float* __restrict__ bhh,
                                                  float* __restrict__ out) {
    int g = blockIdx.x;
    int tid = threadIdx.x, lane = tid & 31, w = tid >> 5;
    __shared__ float sq[64];
    __shared__ float sh[DIM], sc[DIM];
    __shared__ float sgate[128];
    __shared__ float red[4], sr[4][DIM], sd[4];
    __shared__ int   sse[2];

    if (tid < 2) {
        int target = g + tid;
        int lo = 0, hi = NN;
        while (lo < hi) { int mid = (lo + hi) >> 1; if (gidx[mid] < target) lo = mid + 1; else hi = mid; }
        sse[tid] = lo;
    }
    if (tid < 64) sq[tid] = 0.f;
    if (tid < DIM) { sh[tid] = 0.f; sc[tid] = 0.f; }
    __syncthreads();
    int s = sse[0], e = sse[1];

    float bsum = bih[tid] + bhh[tid];

    for (int step = 0; step < 3; step++) {
        float gv = bsum;
        for (int i = 0; i < 64; i++) gv = fmaf(sq[i], g_lwihT[i * 128 + tid], gv);
        for (int i = 0; i < DIM; i++) gv = fmaf(sh[i], g_lwhhT[i * 128 + tid], gv);
        sgate[tid] = gv;
        __syncthreads();
        if (tid < DIM) {
            float si = 1.f / (1.f + expf(-sgate[tid]));
            float sf = 1.f / (1.f + expf(-sgate[32 + tid]));
            float gg = tanhf(sgate[64 + tid]);
            float so = 1.f / (1.f + expf(-sgate[96 + tid]));
            float cc = sf * sc[tid] + si * gg;
            sc[tid] = cc;
            sh[tid] = so * tanhf(cc);
        }
        __syncthreads();

        float qv = sh[lane];
        float mx = -INFINITY;
        for (int n = s + w; n < e; n += 4) {
            float v = g_x[n * DIM + lane] * qv;
#pragma unroll
            for (int off = 16; off; off >>= 1) v += __shfl_xor_sync(0xffffffffu, v, off);
            mx = fmaxf(mx, v);
        }
        if (lane == 0) red[w] = mx;
        __syncthreads();
        mx = fmaxf(fmaxf(red[0], red[1]), fmaxf(red[2], red[3]));
        float denom = 0.f, racc = 0.f;
        for (int n = s + w; n < e; n += 4) {
            float xo = g_x[n * DIM + lane];
            float v = xo * qv;
#pragma unroll
            for (int off = 16; off; off >>= 1) v += __shfl_xor_sync(0xffffffffu, v, off);
            float ex = __expf(v - mx);
            denom += ex;
            racc = fmaf(ex, xo, racc);
        }
        sr[w][lane] = racc;
        if (lane == 0) sd[w] = denom;
        __syncthreads();
        if (w == 0) {
            float r = sr[0][lane] + sr[1][lane] + sr[2][lane] + sr[3][lane];
            float d = sd[0] + sd[1] + sd[2] + sd[3];
            r = (d > 0.f) ? r / d : 0.f;
            sq[lane] = sh[lane];
            sq[32 + lane] = r;
        }
        __syncthreads();
    }

    if (tid < 64) out[g * 64 + tid] = sq[tid];
    int cnt = (e - s) * DIM;
    const float* xs = g_x + s * DIM;
    float* od = out + NB * 64 + s * DIM;
    for (int i = tid; i < cnt; i += 128) od[i] = xs[i];
}

// ---------------- launch ----------------
extern "C" void kernel_launch(void* const* d_in, const int* in_sizes, int n_in,
                              void* d_out, int out_size) {
    const float* nf        = (const float*)d_in[0];
    const float* ef        = (const float*)d_in[1];
    const float* lin0_w    = (const float*)d_in[2];
    const float* lin0_b    = (const float*)d_in[3];
    const float* nn_w1     = (const float*)d_in[4];
    const float* nn_b1     = (const float*)d_in[5];
    const float* nn_w2     = (const float*)d_in[6];
    const float* nn_b2     = (const float*)d_in[7];
    const float* conv_bias = (const float*)d_in[8];
    const float* gru_wih   = (const float*)d_in[9];
    const float* gru_whh   = (const float*)d_in[10];
    const float* gru_bih   = (const float*)d_in[11];
    const float* gru_bhh   = (const float*)d_in[12];
    const float* lstm_wih  = (const float*)d_in[13];
    const float* lstm_whh  = (const float*)d_in[14];
    const float* lstm_bih  = (const float*)d_in[15];
    const float* lstm_bhh  = (const float*)d_in[16];
    const int*   ei        = (const int*)d_in[17];
    const int*   gidx      = (const int*)d_in[18];

    static cudaStream_t s2 = 0;
    static cudaEvent_t evA = 0, evB = 0;
    if (!s2) {
        cudaFuncSetAttribute(gemm_fused_kernel, cudaFuncAttributeMaxDynamicSharedMemorySize,
                             SMEM_GEMM_TOTAL);
        cudaFuncSetAttribute(gru_mma_kernel, cudaFuncAttributeMaxDynamicSharedMemorySize,
                             GRU_SMEM);
        cudaStreamCreateWithFlags(&s2, cudaStreamNonBlocking);
        cudaEventCreateWithFlags(&evA, cudaEventDisableTiming);
        cudaEventCreateWithFlags(&evB, cudaEventDisableTiming);
    }

    prep_kernel<<<512, 256>>>(lin0_w, nn_w1, gru_wih, gru_whh, lstm_wih, lstm_whh, nn_w2, nn_b2);
    cudaEventRecord(evA, 0);
    cudaStreamWaitEvent(s2, evA, 0);
    lin0_kernel<<<(NN + 63) / 64, 256, 0, s2>>>(nf, lin0_b);   // zeroes g_cnt / g_acc
    deg_kernel<<<(NE + 255) / 256, 256, 0, s2>>>(ei);
    cudaEventRecord(evB, s2);
    gemm_fused_kernel<<<MPAD / 128, 256, SMEM_GEMM_TOTAL>>>(ef, nn_b1);  // overlaps lin0/deg
    cudaStreamWaitEvent(0, evB, 0);

    for (int t = 0; t < 3; t++) {
        conv_kernel<<<NE / 8, 256>>>(ei);
        gru_mma_kernel<<<(NN + 63) / 64, 256, GRU_SMEM>>>(conv_bias, gru_bih, gru_bhh);
    }

    s2s_kernel<<<NB, 128>>>(gidx, lstm_bih, lstm_bhh, (float*)d_out);
}

// round 16
// speedup vs baseline: 1.3535x; 1.0122x over previous
#include <cuda_runtime.h>
#include <cuda_fp16.h>
#include <math.h>
#include <stdint.h>

#define NN   100000
#define NE   250000
#define NB   2000
#define FIN  75
#define DIM  32
#define HID  128
#define NOUT 1024           // DIM*DIM
#define MPAD 250112         // 1954 * 128

// ---------------- scratch (static __device__, no allocation) ----------------
__device__ __align__(16) __half g_ewb[(size_t)MPAD * NOUT];  // edge weights fp16, [o][i] per edge
__device__ __align__(16) __half g_w2b[NOUT * HID];           // W2 fp16, column-permuted (c' = o*32+i)
__device__ __align__(16) __half g_gruB[128 * 64];            // GRU combined weights [128 x 64] fp16
__device__ float g_b2p[NOUT];                                // b2 permuted
__device__ float g_x[NN * DIM];                 // node state
__device__ float g_acc[NN * DIM];               // conv scatter accumulator
__device__ int   g_cnt[NN];                     // in-degree
// transposed weights
__device__ float g_w0T[FIN * DIM];
__device__ float g_w1T[11 * HID];
__device__ float g_lwihT[64 * 128];
__device__ float g_lwhhT[DIM * 128];

__device__ __forceinline__ uint32_t smem_u32(const void* p) {
    uint32_t a;
    asm("{ .reg .u64 t; cvta.to.shared.u64 t, %1; cvt.u32.u64 %0, t; }" : "=r"(a) : "l"(p));
    return a;
}
__device__ __forceinline__ void cp_async16(uint32_t dst, const void* src) {
    asm volatile("cp.async.cg.shared.global [%0], [%1], 16;" :: "r"(dst), "l"(src));
}
#define CP_COMMIT() asm volatile("cp.async.commit_group;" ::: "memory")
#define CP_WAIT0()  asm volatile("cp.async.wait_group 0;" ::: "memory")

__device__ __forceinline__ void mma_fp16(float* c, const uint32_t* a, uint32_t b0, uint32_t b1) {
    asm volatile(
        "mma.sync.aligned.m16n8k16.row.col.f32.f16.f16.f32 "
        "{%0,%1,%2,%3}, {%4,%5,%6,%7}, {%8,%9}, {%0,%1,%2,%3};"
        : "+f"(c[0]), "+f"(c[1]), "+f"(c[2]), "+f"(c[3])
        : "r"(a[0]), "r"(a[1]), "r"(a[2]), "r"(a[3]), "r"(b0), "r"(b1));
}

// ---------------- prep: transposes + fp16 W2 (col-permuted) + GRU combined B ----------------
__global__ void prep_kernel(const float* __restrict__ w0, const float* __restrict__ w1,
                            const float* __restrict__ gwih, const float* __restrict__ gwhh,
                            const float* __restrict__ lwih, const float* __restrict__ lwhh,
                            const float* __restrict__ w2, const float* __restrict__ b2) {
    int t = blockIdx.x * 256 + threadIdx.x;
    if (t < FIN * DIM) { int i = t / DIM, o = t % DIM; g_w0T[t] = w0[o * FIN + i]; }
    if (t < 11 * HID)  { int i = t / HID, j = t % HID; g_w1T[t] = w1[j * 11 + i]; }
    if (t < 64 * 128)  { int i = t / 128, r = t % 128; g_lwihT[t] = lwih[r * 64 + i]; }
    if (t < DIM * 128) { int i = t / 128, r = t % 128; g_lwhhT[t] = lwhh[r * DIM + i]; }
    if (t < NOUT) { int corig = (t & 31) * 32 + (t >> 5); g_b2p[t] = b2[corig]; }
    if (t < 128 * 64) {
        int np = t >> 6, k = t & 63;
        float v = 0.f;
        int o = np & 31, blk = np >> 5;       // blk: 0=r-sum 1=z-sum 2=gi_n 3=gh_n
        if (blk == 0) v = (k < 32) ? gwih[o * DIM + k]          : gwhh[o * DIM + (k - 32)];
        else if (blk == 1) v = (k < 32) ? gwih[(32 + o) * DIM + k]   : gwhh[(32 + o) * DIM + (k - 32)];
        else if (blk == 2) v = (k < 32) ? gwih[(64 + o) * DIM + k]   : 0.f;
        else               v = (k < 32) ? 0.f                        : gwhh[(64 + o) * DIM + (k - 32)];
        g_gruB[t] = __float2half(v);
    }
    if (t < NOUT * HID) {
        int cp = t / HID, k = t % HID;
        int corig = (cp & 31) * 32 + (cp >> 5);
        g_w2b[t] = __float2half(w2[corig * HID + k]);
    }
}

__global__ void deg_kernel(const int* __restrict__ ei) {
    int e = blockIdx.x * 256 + threadIdx.x;
    if (e < NE) atomicAdd(&g_cnt[ei[NE + e]], 1);
}

// ---------------- lin0: 64 nodes/block, 8 nodes/warp; also zeroes g_cnt / g_acc ----------------
__global__ void __launch_bounds__(256) lin0_kernel(const float* __restrict__ nf,
                                                   const float* __restrict__ b) {
    __shared__ float sf[64][FIN + 1];
    int tid = threadIdx.x;
    int base = blockIdx.x * 64;
    for (int idx = tid; idx < 64 * FIN; idx += 256) {
        int n = idx / FIN, i = idx % FIN;
        int node = base + n;
        sf[n][i] = (node < NN) ? nf[(size_t)node * FIN + i] : 0.f;
    }
    __syncthreads();
    int warp = tid >> 5, o = tid & 31;
    int n0 = warp * 8;
    float acc[8];
    float bo = b[o];
#pragma unroll
    for (int n = 0; n < 8; n++) acc[n] = bo;
    for (int i = 0; i < FIN; i++) {
        float w = g_w0T[i * DIM + o];
#pragma unroll
        for (int n = 0; n < 8; n++) acc[n] = fmaf(sf[n0 + n][i], w, acc[n]);
    }
#pragma unroll
    for (int n = 0; n < 8; n++) {
        int node = base + n0 + n;
        if (node < NN) {
            g_x[node * DIM + o] = fmaxf(acc[n], 0.f);
            g_acc[node * DIM + o] = 0.f;
            if (o == 0) g_cnt[node] = 0;
        }
    }
}

// ---- fused GEMM: per CTA of 128 edges; cp.async B slabs, 2 syncs/slab ----
#define SM_A     0
#define SM_B     32768
#define SM_CSTG  65536
#define SM_SEF   65536
#define SM_W1T   (65536 + 6144)
#define SM_B1    (65536 + 6144 + 5632)
#define SM_BIAS  100352
#define SMEM_GEMM_TOTAL 104448
#define CSTRIDE 272

__global__ void __launch_bounds__(256) gemm_fused_kernel(const float* __restrict__ ef,
                                                         const float* __restrict__ b1) {
    extern __shared__ __align__(16) char smem[];
    uint32_t sbase = smem_u32(smem);
    float* sef   = (float*)(smem + SM_SEF);
    float* sw1t  = (float*)(smem + SM_W1T);
    float* sb1   = (float*)(smem + SM_B1);
    float* sbias = (float*)(smem + SM_BIAS);
    int tid = threadIdx.x, lane = tid & 31, wid = tid >> 5;
    int e0 = blockIdx.x * 128;

    // issue cp.async for B slab 0 (overlaps aux loads + A build)
#pragma unroll
    for (int it = 0; it < 8; it++) {
        int idx = tid + it * 256;
        int row = idx >> 4, c = idx & 15;
        int cs = (c & 8) | ((c ^ row) & 7);
        cp_async16(sbase + SM_B + row * 256 + cs * 16,
                   (const char*)g_w2b + (((size_t)row) * HID + c * 8) * 2);
    }
    CP_COMMIT();

    for (int idx = tid; idx < 128 * 11; idx += 256) {
        int r = idx / 11, i = idx % 11;
        int e = e0 + r;
        sef[r * 12 + i] = (e < NE) ? ef[(size_t)e * 11 + i] : 0.f;
    }
    for (int idx = tid; idx < 11 * HID; idx += 256) sw1t[idx] = g_w1T[idx];
    if (tid < 128) sb1[tid] = b1[tid];
#pragma unroll
    for (int l = 0; l < 4; l++) sbias[tid + l * 256] = g_b2p[tid + l * 256];
    __syncthreads();

    // build A tile: hw = relu(ef @ W1^T + b1), fp16, xor-swizzled
#pragma unroll
    for (int ci = 0; ci < 8; ci++) {
        int cidx = tid + ci * 256;
        int row = cidx >> 4, c = cidx & 15;
        int k0 = c * 8;
        float v[8];
#pragma unroll
        for (int j = 0; j < 8; j++) v[j] = sb1[k0 + j];
#pragma unroll
        for (int i = 0; i < 11; i++) {
            float e_ = sef[row * 12 + i];
#pragma unroll
            for (int j = 0; j < 8; j++) v[j] = fmaf(e_, sw1t[i * HID + k0 + j], v[j]);
        }
        uint32_t p[4];
#pragma unroll
        for (int j = 0; j < 4; j++) {
            __half2 h = __floats2half2_rn(fmaxf(v[2 * j], 0.f), fmaxf(v[2 * j + 1], 0.f));
            p[j] = *(uint32_t*)&h;
        }
        int cs = (c & 8) | ((c ^ row) & 7);
        *(uint4*)(smem + SM_A + row * 256 + cs * 16) = make_uint4(p[0], p[1], p[2], p[3]);
    }
    CP_WAIT0();
    __syncthreads();     // A built, B0 in smem, aux consumed

    int wm = (wid & 3) * 32;
    int wn = (wid >> 2) * 64;
    int g = lane >> 2, tg = lane & 3;

    for (int nb = 0; nb < 8; nb++) {
        float acc[2][8][4];
#pragma unroll
        for (int mb = 0; mb < 2; mb++)
#pragma unroll
            for (int nbb = 0; nbb < 8; nbb++)
#pragma unroll
                for (int q = 0; q < 4; q++) acc[mb][nbb][q] = 0.f;

#pragma unroll
        for (int ks = 0; ks < 8; ks++) {
            int ck0 = ks * 2;
            uint32_t a[2][4], b[4][4];
#pragma unroll
            for (int mb = 0; mb < 2; mb++) {
                int row = wm + mb * 16 + (lane & 7) + ((lane >> 3) & 1) * 8;
                int ck = ck0 + (lane >> 4);
                int cs = (ck & 8) | ((ck ^ row) & 7);
                uint32_t addr = sbase + SM_A + row * 256 + cs * 16;
                asm volatile("ldmatrix.sync.aligned.m8n8.x4.shared.b16 {%0,%1,%2,%3}, [%4];"
                             : "=r"(a[mb][0]), "=r"(a[mb][1]), "=r"(a[mb][2]), "=r"(a[mb][3])
                             : "r"(addr));
            }
#pragma unroll
            for (int nb4 = 0; nb4 < 4; nb4++) {
                int t = lane >> 3, r = lane & 7;
                int n = wn + nb4 * 16 + r + (t >> 1) * 8;
                int ck = ck0 + (t & 1);
                int cs = (ck & 8) | ((ck ^ n) & 7);
                uint32_t addr = sbase + SM_B + n * 256 + cs * 16;
                asm volatile("ldmatrix.sync.aligned.m8n8.x4.shared.b16 {%0,%1,%2,%3}, [%4];"
                             : "=r"(b[nb4][0]), "=r"(b[nb4][1]), "=r"(b[nb4][2]), "=r"(b[nb4][3])
                             : "r"(addr));
            }
#pragma unroll
            for (int mb = 0; mb < 2; mb++)
#pragma unroll
                for (int nbb = 0; nbb < 8; nbb++)
                    mma_fp16(acc[mb][nbb], a[mb], b[nbb >> 1][(nbb & 1) * 2], b[nbb >> 1][(nbb & 1) * 2 + 1]);
        }

        // stage C (register -> CSTG; no conflict with A/B reads, no sync needed before)
#pragma unroll
        for (int mb = 0; mb < 2; mb++)
#pragma unroll
            for (int nbb = 0; nbb < 8; nbb++) {
                int rowl = wm + mb * 16 + g;
                int nl = wn + nbb * 8 + tg * 2;
                float bb0 = sbias[nb * 128 + nl], bb1 = sbias[nb * 128 + nl + 1];
                float* c = acc[mb][nbb];
                __half2 p0 = __floats2half2_rn(c[0] + bb0, c[1] + bb1);
                __half2 p1 = __floats2half2_rn(c[2] + bb0, c[3] + bb1);
                *(uint32_t*)(smem + SM_CSTG + rowl * CSTRIDE + nl * 2) = *(uint32_t*)&p0;
                *(uint32_t*)(smem + SM_CSTG + (rowl + 8) * CSTRIDE + nl * 2) = *(uint32_t*)&p1;
            }
        __syncthreads();   // all mma done (B free), CSTG complete

        // issue cp.async for next B slab — overlaps the global writeback below
        if (nb < 7) {
#pragma unroll
            for (int it = 0; it < 8; it++) {
                int idx = tid + it * 256;
                int row = idx >> 4, c = idx & 15;
                int cs = (c & 8) | ((c ^ row) & 7);
                cp_async16(sbase + SM_B + row * 256 + cs * 16,
                           (const char*)g_w2b + (((size_t)((nb + 1) * 128 + row)) * HID + c * 8) * 2);
            }
            CP_COMMIT();
        }

        __half* dst = g_ewb + (size_t)e0 * NOUT + nb * 128;
#pragma unroll
        for (int it = 0; it < 8; it++) {
            int idx = tid + it * 256;
            int row = idx >> 4, c = idx & 15;
            uint4 v = *(const uint4*)(smem + SM_CSTG + row * CSTRIDE + c * 16);
            *(uint4*)(dst + (size_t)row * NOUT + c * 8) = v;
        }
        if (nb < 7) CP_WAIT0();
        __syncthreads();   // CSTG free for next stage; next B ready
    }
}

// ---------------- NNConv: warp per edge, lane = output channel ----------------
__global__ void conv_kernel(const int* __restrict__ ei) {
    int e = blockIdx.x * 8 + (threadIdx.x >> 5);
    if (e >= NE) return;
    int o = threadIdx.x & 31;
    int src = ei[e];
    int dst = ei[NE + e];
    float xv = g_x[src * DIM + o];
    const uint4* w = (const uint4*)(g_ewb + (size_t)e * NOUT + o * 32);
    uint4 w0 = w[0], w1 = w[1], w2 = w[2], w3 = w[3];
    uint32_t ws[16] = {w0.x, w0.y, w0.z, w0.w, w1.x, w1.y, w1.z, w1.w,
                       w2.x, w2.y, w2.z, w2.w, w3.x, w3.y, w3.z, w3.w};
    float acc = 0.f;
#pragma unroll
    for (int i = 0; i < 16; i++) {
        float2 wp = __half22float2(*(__half2*)&ws[i]);
        float x0 = __shfl_sync(0xffffffffu, xv, 2 * i);
        float x1 = __shfl_sync(0xffffffffu, xv, 2 * i + 1);
        acc = fmaf(x0, wp.x, fmaf(x1, wp.y, acc));
    }
    atomicAdd(&g_acc[dst * DIM + o], acc);
}

// ---------------- GRU via mma: 64 nodes/block, gates = [m|h] @ W'^T ----------------
#define GSA   0
#define GSB   8192
#define GSHF  24576
#define GSD   32768
#define GRU_SMEM (32768 + 64 * 132 * 4)   // 66560

__global__ void __launch_bounds__(256) gru_mma_kernel(const float* __restrict__ cbias,
                                                      const float* __restrict__ bih,
                                                      const float* __restrict__ bhh) {
    extern __shared__ __align__(16) char smem[];
    uint32_t sbase = smem_u32(smem);
    float* shf = (float*)(smem + GSHF);
    float* sD  = (float*)(smem + GSD);
    int tid = threadIdx.x, lane = tid & 31, wid = tid >> 5;
    int base = blockIdx.x * 64;

#pragma unroll
    for (int l = 0; l < 4; l++) {
        int idx = tid + l * 256;
        int row = idx >> 3, c = idx & 7;
        int cs = c ^ (row & 7);
        *(uint4*)(smem + GSB + row * 128 + cs * 16) = ((const uint4*)g_gruB)[idx];
    }
#pragma unroll
    for (int l = 0; l < 2; l++) {
        int idx = tid + l * 256;
        int n = idx >> 3, c = idx & 7;
        int node = base + n;
        float v[8];
        if (node < NN) {
            if (c < 4) {
                int k0 = c * 8;
                float4 a0 = *(float4*)&g_acc[node * DIM + k0];
                float4 a1 = *(float4*)&g_acc[node * DIM + k0 + 4];
                float4 cb0 = *(const float4*)&cbias[k0];
                float4 cb1 = *(const float4*)&cbias[k0 + 4];
                int cnt = g_cnt[node]; if (cnt < 1) cnt = 1;
                float fc = (float)cnt;
                v[0] = fmaxf(a0.x / fc + cb0.x, 0.f);
                v[1] = fmaxf(a0.y / fc + cb0.y, 0.f);
                v[2] = fmaxf(a0.z / fc + cb0.z, 0.f);
                v[3] = fmaxf(a0.w / fc + cb0.w, 0.f);
                v[4] = fmaxf(a1.x / fc + cb1.x, 0.f);
                v[5] = fmaxf(a1.y / fc + cb1.y, 0.f);
                v[6] = fmaxf(a1.z / fc + cb1.z, 0.f);
                v[7] = fmaxf(a1.w / fc + cb1.w, 0.f);
                *(float4*)&g_acc[node * DIM + k0]     = make_float4(0.f, 0.f, 0.f, 0.f);
                *(float4*)&g_acc[node * DIM + k0 + 4] = make_float4(0.f, 0.f, 0.f, 0.f);
            } else {
                int k0 = (c - 4) * 8;
                float4 h0 = *(float4*)&g_x[node * DIM + k0];
                float4 h1 = *(float4*)&g_x[node * DIM + k0 + 4];
                v[0] = h0.x; v[1] = h0.y; v[2] = h0.z; v[3] = h0.w;
                v[4] = h1.x; v[5] = h1.y; v[6] = h1.z; v[7] = h1.w;
                *(float4*)&shf[n * 32 + k0]     = h0;
                *(float4*)&shf[n * 32 + k0 + 4] = h1;
            }
        } else {
#pragma unroll
            for (int j = 0; j < 8; j++) v[j] = 0.f;
            if (c >= 4) {
                int k0 = (c - 4) * 8;
                *(float4*)&shf[n * 32 + k0]     = make_float4(0.f, 0.f, 0.f, 0.f);
                *(float4*)&shf[n * 32 + k0 + 4] = make_float4(0.f, 0.f, 0.f, 0.f);
            }
        }
        uint32_t p[4];
#pragma unroll
        for (int j = 0; j < 4; j++) {
            __half2 h = __floats2half2_rn(v[2 * j], v[2 * j + 1]);
            p[j] = *(uint32_t*)&h;
        }
        int cs = c ^ (n & 7);
        *(uint4*)(smem + GSA + n * 128 + cs * 16) = make_uint4(p[0], p[1], p[2], p[3]);
    }
    __syncthreads();

    int wm = (wid & 3) * 16;
    int wn = (wid >> 2) * 64;
    float acc[8][4];
#pragma unroll
    for (int nbb = 0; nbb < 8; nbb++)
#pragma unroll
        for (int q = 0; q < 4; q++) acc[nbb][q] = 0.f;

#pragma unroll
    for (int ks = 0; ks < 4; ks++) {
        int ck0 = ks * 2;
        uint32_t a[4], b[4][4];
        {
            int row = wm + (lane & 7) + ((lane >> 3) & 1) * 8;
            int ck = ck0 + (lane >> 4);
            int cs = ck ^ (row & 7);
            uint32_t addr = sbase + GSA + row * 128 + cs * 16;
            asm volatile("ldmatrix.sync.aligned.m8n8.x4.shared.b16 {%0,%1,%2,%3}, [%4];"
                         : "=r"(a[0]), "=r"(a[1]), "=r"(a[2]), "=r"(a[3]) : "r"(addr));
        }
#pragma unroll
        for (int nb4 = 0; nb4 < 4; nb4++) {
            int t = lane >> 3, r = lane & 7;
            int n = wn + nb4 * 16 + r + (t >> 1) * 8;
            int ck = ck0 + (t & 1);
            int cs = ck ^ (n & 7);
            uint32_t addr = sbase + GSB + n * 128 + cs * 16;
            asm volatile("ldmatrix.sync.aligned.m8n8.x4.shared.b16 {%0,%1,%2,%3}, [%4];"
                         : "=r"(b[nb4][0]), "=r"(b[nb4][1]), "=r"(b[nb4][2]), "=r"(b[nb4][3])
                         : "r"(addr));
        }
#pragma unroll
        for (int nbb = 0; nbb < 8; nbb++)
            mma_fp16(acc[nbb], a, b[nbb >> 1][(nbb & 1) * 2], b[nbb >> 1][(nbb & 1) * 2 + 1]);
    }

    int g = lane >> 2, tg = lane & 3;
#pragma unroll
    for (int nbb = 0; nbb < 8; nbb++) {
        int rowl = wm + g;
        int nl = wn + nbb * 8 + tg * 2;
        float* c = acc[nbb];
        *(float2*)&sD[rowl * 132 + nl] = make_float2(c[0], c[1]);
        *(float2*)&sD[(rowl + 8) * 132 + nl] = make_float2(c[2], c[3]);
    }
    __syncthreads();

    float br  = bih[lane] + bhh[lane];
    float bz  = bih[32 + lane] + bhh[32 + lane];
    float bin = bih[64 + lane];
    float bhn = bhh[64 + lane];
#pragma unroll
    for (int l = 0; l < 8; l++) {
        int idx = tid + l * 256;
        int n = idx >> 5, o = idx & 31;
        int node = base + n;
        if (node < NN) {
            const float* d = &sD[n * 132];
            float r = 1.f / (1.f + expf(-(d[o] + br)));
            float z = 1.f / (1.f + expf(-(d[32 + o] + bz)));
            float nv = tanhf(d[64 + o] + bin + r * (d[96 + o] + bhn));
            float h = shf[n * 32 + o];
            g_x[node * DIM + o] = (1.f - z) * nv + z * h;
        }
    }
}

// ---------------- fused Set2Set: one block per graph, all 3 steps + writeout ----------------
__global__ void __launch_bounds__(128) s2s_kernel(const int* __restrict__ gidx,
                                                  const float* __restrict__ bih,
                                                  const float* __restrict__ bhh,
                                                  float* __restrict__ out) {
    int g = blockIdx.x;
    int tid = threadIdx.x, lane = tid & 31, w = tid >> 5;
    __shared__ float sq[64];
    __shared__ float sh[DIM], sc[DIM];
    __shared__ float sgate[128];
    __shared__ float red[4], sr[4][DIM], sd[4];
    __shared__ int   sse[2];

    if (tid < 2) {
        int target = g + tid;
        int lo = 0, hi = NN;
        while (lo < hi) { int mid = (lo + hi) >> 1; if (gidx[mid] < target) lo = mid + 1; else hi = mid; }
        sse[tid] = lo;
    }
    if (tid < 64) sq[tid] = 0.f;
    if (tid < DIM) { sh[tid] = 0.f; sc[tid] = 0.f; }
    __syncthreads();
    int s = sse[0], e = sse[1];

    float bsum = bih[tid] + bhh[tid];

    for (int step = 0; step < 3; step++) {
        float gv = bsum;
        for (int i = 0; i < 64; i++) gv = fmaf(sq[i], g_lwihT[i * 128 + tid], gv);
        for (int i = 0; i < DIM; i++) gv = fmaf(sh[i], g_lwhhT[i * 128 + tid], gv);
        sgate[tid] = gv;
        __syncthreads();
        if (tid < DIM) {
            float si = 1.f / (1.f + expf(-sgate[tid]));
            float sf = 1.f / (1.f + expf(-sgate[32 + tid]));
            float gg = tanhf(sgate[64 + tid]);
            float so = 1.f / (1.f + expf(-sgate[96 + tid]));
            float cc = sf * sc[tid] + si * gg;
            sc[tid] = cc;
            sh[tid] = so * tanhf(cc);
        }
        __syncthreads();

        float qv = sh[lane];
        float mx = -INFINITY;
        for (int n = s + w; n < e; n += 4) {
            float v = g_x[n * DIM + lane] * qv;
#pragma unroll
            for (int off = 16; off; off >>= 1) v += __shfl_xor_sync(0xffffffffu, v, off);
            mx = fmaxf(mx, v);
        }
        if (lane == 0) red[w] = mx;
        __syncthreads();
        mx = fmaxf(fmaxf(red[0], red[1]), fmaxf(red[2], red[3]));
        float denom = 0.f, racc = 0.f;
        for (int n = s + w; n < e; n += 4) {
            float xo = g_x[n * DIM + lane];
            float v = xo * qv;
#pragma unroll
            for (int off = 16; off; off >>= 1) v += __shfl_xor_sync(0xffffffffu, v, off);
            float ex = __expf(v - mx);
            denom += ex;
            racc = fmaf(ex, xo, racc);
        }
        sr[w][lane] = racc;
        if (lane == 0) sd[w] = denom;
        __syncthreads();
        if (w == 0) {
            float r = sr[0][lane] + sr[1][lane] + sr[2][lane] + sr[3][lane];
            float d = sd[0] + sd[1] + sd[2] + sd[3];
            r = (d > 0.f) ? r / d : 0.f;
            sq[lane] = sh[lane];
            sq[32 + lane] = r;
        }
        __syncthreads();
    }

    if (tid < 64) out[g * 64 + tid] = sq[tid];
    int cnt = (e - s) * DIM;
    const float* xs = g_x + s * DIM;
    float* od = out + NB * 64 + s * DIM;
    for (int i = tid; i < cnt; i += 128) od[i] = xs[i];
}

// ---------------- launch ----------------
extern "C" void kernel_launch(void* const* d_in, const int* in_sizes, int n_in,
                              void* d_out, int out_size) {
    const float* nf        = (const float*)d_in[0];
    const float* ef        = (const float*)d_in[1];
    const float* lin0_w    = (const float*)d_in[2];
    const float* lin0_b    = (const float*)d_in[3];
    const float* nn_w1     = (const float*)d_in[4];
    const float* nn_b1     = (const float*)d_in[5];
    const float* nn_w2     = (const float*)d_in[6];
    const float* nn_b2     = (const float*)d_in[7];
    const float* conv_bias = (const float*)d_in[8];
    const float* gru_wih   = (const float*)d_in[9];
    const float* gru_whh   = (const float*)d_in[10];
    const float* gru_bih   = (const float*)d_in[11];
    const float* gru_bhh   = (const float*)d_in[12];
    const float* lstm_wih  = (const float*)d_in[13];
    const float* lstm_whh  = (const float*)d_in[14];
    const float* lstm_bih  = (const float*)d_in[15];
    const float* lstm_bhh  = (const float*)d_in[16];
    const int*   ei        = (const int*)d_in[17];
    const int*   gidx      = (const int*)d_in[18];

    static cudaStream_t s2 = 0;
    static cudaEvent_t evA = 0, evB = 0;
    if (!s2) {
        cudaFuncSetAttribute(gemm_fused_kernel, cudaFuncAttributeMaxDynamicSharedMemorySize,
                             SMEM_GEMM_TOTAL);
        cudaFuncSetAttribute(gru_mma_kernel, cudaFuncAttributeMaxDynamicSharedMemorySize,
                             GRU_SMEM);
        cudaStreamCreateWithFlags(&s2, cudaStreamNonBlocking);
        cudaEventCreateWithFlags(&evA, cudaEventDisableTiming);
        cudaEventCreateWithFlags(&evB, cudaEventDisableTiming);
    }

    prep_kernel<<<512, 256>>>(lin0_w, nn_w1, gru_wih, gru_whh, lstm_wih, lstm_whh, nn_w2, nn_b2);
    cudaEventRecord(evA, 0);
    cudaStreamWaitEvent(s2, evA, 0);
    lin0_kernel<<<(NN + 63) / 64, 256, 0, s2>>>(nf, lin0_b);   // zeroes g_cnt / g_acc
    deg_kernel<<<(NE + 255) / 256, 256, 0, s2>>>(ei);
    cudaEventRecord(evB, s2);
    gemm_fused_kernel<<<MPAD / 128, 256, SMEM_GEMM_TOTAL>>>(ef, nn_b1);  // overlaps lin0/deg
    cudaStreamWaitEvent(0, evB, 0);

    for (int t = 0; t < 3; t++) {
        conv_kernel<<<NE / 8, 256>>>(ei);
        gru_mma_kernel<<<(NN + 63) / 64, 256, GRU_SMEM>>>(conv_bias, gru_bih, gru_bhh);
    }

    s2s_kernel<<<NB, 128>>>(gidx, lstm_bih, lstm_bhh, (float*)d_out);
}